// round 2
// baseline (speedup 1.0000x reference)
#include <cuda_runtime.h>
#include <cstdint>

// ---------------- problem constants ----------------
#define Rn     20
#define NB     4
#define Hh     480
#define Ww     640
#define hh     120
#define ww     160
#define FC     32
#define DC     32
#define CO2    4
#define NPIX   (hh*ww)           // 19200
#define NPIXH  (Hh*Ww)           // 307200
#define TOTPX  (Rn*NB*NPIX)      // 1,536,000
#define BIAS_I 1282              // W//w//2 + (H//h//2)*W
#define EPSF   1e-6f
#define BETAF  0.01f

// ---------------- device scratch (globals; no allocation) ----------------
__device__ float g_xT[(size_t)NB*Hh*Ww*FC];       // [b][y][x][c]
__device__ float g_wattT[32*3*3*32];              // [ci][ky][kx][co]
__device__ float g_wpostT[32*3*3*4];              // [ci][ky][kx][co]
__device__ float g_rg[TOTPX];                     // pooled gt map
__device__ float g_cx[TOTPX];                     // sample pixel coord x
__device__ float g_cy[TOTPX];                     // sample pixel coord y
__device__ float g_feat[(size_t)TOTPX*FC];        // [rb][y][x][c]
__device__ float g_attd[(size_t)Rn*NB*DC*NPIX];   // [rb][c][y][x]
__device__ float g_ds[(size_t)Rn*NB*CO2*NPIX];    // [rb][k][y][x]
__device__ float g_num[Rn];
__device__ float g_den[Rn];

// ---------------- x transpose: [b][c][y][x] -> [b][y][x][c] ----------------
__global__ void k_transpose_x(const float* __restrict__ x) {
    __shared__ float tile[32][33];
    int b = blockIdx.z, y = blockIdx.y, x0 = blockIdx.x * 32;
    for (int c = threadIdx.y; c < 32; c += 8)
        tile[c][threadIdx.x] = x[(((size_t)b*32 + c)*Hh + y)*Ww + x0 + threadIdx.x];
    __syncthreads();
    for (int xx = threadIdx.y; xx < 32; xx += 8)
        g_xT[(((size_t)b*Hh + y)*Ww + x0 + xx)*32 + threadIdx.x] = tile[threadIdx.x][xx];
}

// ---------------- weight transpose [co][ci][ky][kx] -> [ci][ky][kx][co] ----
__global__ void k_transpose_w(const float* __restrict__ wa, const float* __restrict__ wp) {
    int e = blockIdx.x * 256 + threadIdx.x;
    if (e < 32*32*9) {
        int kx = e % 3, t = e / 3; int ky = t % 3; t /= 3; int ci = t % 32; int co = t / 32;
        g_wattT[((ci*3 + ky)*3 + kx)*32 + co] = wa[e];
    }
    if (e < 4*32*9) {
        int kx = e % 3, t = e / 3; int ky = t % 3; t /= 3; int ci = t % 32; int co = t / 32;
        g_wpostT[((ci*3 + ky)*3 + kx)*4 + co] = wp[e];
    }
}

// ---------------- random pooling + coordinate maps ----------------
__global__ void k_pool(const float* __restrict__ gts, const float* __restrict__ rnd) {
    int tid = blockIdx.x * 256 + threadIdx.x;
    if (tid >= TOTPX) return;
    int ox = tid % ww; int t2 = tid / ww;
    int oy = t2 % hh;  t2 /= hh;
    int b  = t2 % NB;  int r = t2 / NB;
    const float* rp = rnd + (size_t)(r*NB + b) * NPIXH;
    const float* gp = gts + (size_t)b * NPIXH;
    int gy0 = oy * 4, gx0 = ox * 4;
    float best = -1.0f; int bi = 0, bj = 0;
    #pragma unroll
    for (int i = 0; i < 4; i++) {
        const float4 rv = *(const float4*)(rp + (size_t)(gy0 + i)*Ww + gx0);
        const float4 gv = *(const float4*)(gp + (size_t)(gy0 + i)*Ww + gx0);
        float rr[4] = {rv.x, rv.y, rv.z, rv.w};
        float gg[4] = {gv.x, gv.y, gv.z, gv.w};
        #pragma unroll
        for (int j = 0; j < 4; j++) {
            float m = (gg[j] > 0.1f) ? rr[j] : 0.0f;
            if (m > best) { best = m; bi = i; bj = j; }
        }
    }
    int row = gy0 + bi, col = gx0 + bj;
    float g = gp[(size_t)row*Ww + col];
    g_rg[tid] = (g < 0.1f) ? 0.0f : g;
    int idx = row * Ww + col + BIAS_I;
    int qy = idx / Ww; int qx = idx - qy * Ww;
    // ix = ((idx%W)/W)*(W-1), iy = ((idx//W)/H)*(H-1)
    g_cx[tid] = ((float)qx / (float)Ww) * (float)(Ww - 1);
    g_cy[tid] = ((float)qy / (float)Hh) * (float)(Hh - 1);
}

// ---------------- bilinear gather: one warp per pixel, lane = channel ------
__global__ void k_sample() {
    int gid  = blockIdx.x * 256 + threadIdx.x;
    int wid  = gid >> 5;
    int lane = threadIdx.x & 31;
    if (wid >= TOTPX) return;
    float cx = g_cx[wid], cy = g_cy[wid];
    float fx = floorf(cx), fy = floorf(cy);
    int x0 = (int)fx, y0 = (int)fy;
    float wx = cx - fx, wy = cy - fy;
    int b = (wid / NPIX) & 3;
    const float* base = g_xT + (size_t)b * Hh * Ww * 32 + lane;
    float acc = 0.0f;
    float w00 = (1.f - wx) * (1.f - wy), w10 = wx * (1.f - wy);
    float w01 = (1.f - wx) * wy,         w11 = wx * wy;
    bool vy0 = (y0 >= 0) && (y0 <= Hh - 1);
    bool vy1 = (y0 + 1 >= 0) && (y0 + 1 <= Hh - 1);
    bool vx0 = (x0 >= 0) && (x0 <= Ww - 1);
    bool vx1 = (x0 + 1 >= 0) && (x0 + 1 <= Ww - 1);
    if (vy0) {
        if (vx0) acc += w00 * base[((size_t)y0*Ww + x0)*32];
        if (vx1) acc += w10 * base[((size_t)y0*Ww + x0 + 1)*32];
    }
    if (vy1) {
        if (vx0) acc += w01 * base[((size_t)(y0+1)*Ww + x0)*32];
        if (vx1) acc += w11 * base[((size_t)(y0+1)*Ww + x0 + 1)*32];
    }
    g_feat[(size_t)wid*32 + lane] = acc;
}

// ---------------- conv1 32->32 3x3 SAME + sigmoid * d -> attd -------------
// out tile 32x8, 256 threads: xg(4)*yy(8)*cog(8); thread = 8px x 4co
__global__ void __launch_bounds__(256) k_conv1(const float* __restrict__ dten,
                                               const float* __restrict__ batt) {
    __shared__ float s_in[16 * 10 * 35];   // [ci][py(10)][px pitch35]
    __shared__ float s_w[16 * 9 * 32];     // [ci][ky][kx][co]
    int rb = blockIdx.z;
    int x0 = blockIdx.x * 32;
    int y0 = blockIdx.y * 8;
    int t = threadIdx.x;
    int xg = t & 3, yy = (t >> 2) & 7, cog = t >> 5;
    float acc[4][8];
    #pragma unroll
    for (int c = 0; c < 4; c++)
        #pragma unroll
        for (int p = 0; p < 8; p++) acc[c][p] = 0.0f;
    const float* featbase = g_feat + (size_t)rb * NPIX * 32;

    for (int ch = 0; ch < 2; ch++) {
        __syncthreads();
        for (int e = t; e < 340 * 16; e += 256) {
            int ci = e & 15; int pos = e >> 4;
            int py = pos / 34, px = pos - py * 34;
            int gy = y0 - 1 + py, gx = x0 - 1 + px;
            float v = 0.0f;
            if (gy >= 0 && gy < hh && gx >= 0 && gx < ww)
                v = featbase[((size_t)gy*ww + gx)*32 + ch*16 + ci];
            s_in[ci*350 + py*35 + px] = v;
        }
        for (int e = t; e < 4608; e += 256)
            s_w[e] = g_wattT[ch*4608 + e];
        __syncthreads();
        #pragma unroll 1
        for (int ci = 0; ci < 16; ci++) {
            const float* srow = s_in + ci * 350;
            #pragma unroll
            for (int ky = 0; ky < 3; ky++) {
                float v[10];
                const float* rp = srow + (yy + ky)*35 + xg*8;
                #pragma unroll
                for (int j = 0; j < 10; j++) v[j] = rp[j];
                #pragma unroll
                for (int kx = 0; kx < 3; kx++) {
                    #pragma unroll
                    for (int cj = 0; cj < 4; cj++) {
                        float wv = s_w[(ci*9 + ky*3 + kx)*32 + cog*4 + cj];
                        #pragma unroll
                        for (int p = 0; p < 8; p++)
                            acc[cj][p] = fmaf(wv, v[p + kx], acc[cj][p]);
                    }
                }
            }
        }
    }
    // epilogue: sigmoid * d, store channel-first
    int b = rb & 3;
    int y = y0 + yy, x = x0 + xg * 8;
    #pragma unroll
    for (int cj = 0; cj < 4; cj++) {
        int co = cog * 4 + cj;
        float bb = batt[co];
        const float* dp = dten + (((size_t)b*DC + co)*hh + y)*ww + x;
        float* op = g_attd + (((size_t)rb*DC + co)*hh + y)*ww + x;
        #pragma unroll
        for (int p = 0; p < 8; p++) {
            float v = acc[cj][p] + bb;
            float att = 1.0f / (1.0f + __expf(-v));
            op[p] = att * dp[p];
        }
    }
}

// ---------------- conv2 32->4 3x3 SAME -> ds -------------------------------
// out tile 32x32, 128 threads: xg(4)*yy(32); thread = 8px x 4co
__global__ void __launch_bounds__(128) k_conv2(const float* __restrict__ bpost) {
    __shared__ float s_in[8 * 34 * 35];    // [ci][py(34)][px pitch35]
    __shared__ float s_w[32 * 9 * 4];      // [ci][ky][kx][co]
    int rb = blockIdx.z;
    int x0 = blockIdx.x * 32;
    int y0 = blockIdx.y * 32;
    int t = threadIdx.x;
    int xg = t & 3, yy = t >> 2;
    float acc[4][8];
    #pragma unroll
    for (int c = 0; c < 4; c++)
        #pragma unroll
        for (int p = 0; p < 8; p++) acc[c][p] = 0.0f;
    for (int e = t; e < 1152; e += 128) s_w[e] = g_wpostT[e];
    const float* abase = g_attd + (size_t)rb * DC * NPIX;

    for (int ch = 0; ch < 4; ch++) {
        __syncthreads();
        for (int e = t; e < 34 * 34 * 8; e += 128) {
            int px = e % 34; int t3 = e / 34;
            int py = t3 % 34; int ci = t3 / 34;
            int gy = y0 - 1 + py, gx = x0 - 1 + px;
            float v = 0.0f;
            if (gy >= 0 && gy < hh && gx >= 0 && gx < ww)
                v = abase[((size_t)(ch*8 + ci)*hh + gy)*ww + gx];
            s_in[ci*1190 + py*35 + px] = v;
        }
        __syncthreads();
        #pragma unroll 1
        for (int ci = 0; ci < 8; ci++) {
            const float* srow = s_in + ci * 1190;
            int cig = ch * 8 + ci;
            #pragma unroll
            for (int ky = 0; ky < 3; ky++) {
                float v[10];
                const float* rp = srow + (yy + ky)*35 + xg*8;
                #pragma unroll
                for (int j = 0; j < 10; j++) v[j] = rp[j];
                #pragma unroll
                for (int kx = 0; kx < 3; kx++) {
                    #pragma unroll
                    for (int cj = 0; cj < 4; cj++) {
                        float wv = s_w[cig*36 + (ky*3 + kx)*4 + cj];
                        #pragma unroll
                        for (int p = 0; p < 8; p++)
                            acc[cj][p] = fmaf(wv, v[p + kx], acc[cj][p]);
                    }
                }
            }
        }
    }
    int y = y0 + yy, x = x0 + xg * 8;
    if (y < hh) {
        #pragma unroll
        for (int cj = 0; cj < 4; cj++) {
            float bb = bpost[cj];
            float* op = g_ds + (((size_t)rb*CO2 + cj)*hh + y)*ww + x;
            #pragma unroll
            for (int p = 0; p < 8; p++) op[p] = acc[cj][p] + bb;
        }
    }
}

// ---------------- zero accumulators ----------------
__global__ void k_zero() {
    int t = threadIdx.x;
    if (t < Rn) { g_num[t] = 0.0f; g_den[t] = 0.0f; }
}

// ---------------- log-grad + smooth L1 + reduce ----------------
__global__ void k_loss() {
    int r = blockIdx.x >> 5;          // 20
    int chunk = blockIdx.x & 31;      // 32 chunks of 2400 pixels over b*h*w
    float num = 0.0f, den = 0.0f;
    const int dy[4] = {0, 1, 1, 1};
    const int dx[4] = {1, 1, 0, -1};
    for (int j = chunk*2400 + threadIdx.x; j < (chunk + 1)*2400; j += 256) {
        int b = j / NPIX; int p = j - b * NPIX;
        int y = p / ww, x = p - y * ww;
        const float* rgp = g_rg + (size_t)(r*NB + b) * NPIX;
        float c = rgp[p];
        if (c > 0.1f) {
            float logc = __logf(c + EPSF);
            const float* dsp = g_ds + (size_t)(r*NB + b) * CO2 * NPIX + p;
            #pragma unroll
            for (int k = 0; k < 4; k++) {
                int yn = y + dy[k], xn = x + dx[k];
                if (yn < hh && xn >= 0 && xn < ww) {
                    float nb = rgp[yn*ww + xn];
                    if (nb > 0.1f) {
                        float grad = logc - __logf(nb + EPSF);
                        float a = fabsf(dsp[k*NPIX] - grad);
                        float s = (a < BETAF) ? (0.5f/BETAF)*a*a : a - 0.5f*BETAF;
                        num += s; den += 1.0f;
                    }
                }
            }
        }
    }
    // warp reduce then atomics (per warp)
    #pragma unroll
    for (int o = 16; o > 0; o >>= 1) {
        num += __shfl_down_sync(0xffffffffu, num, o);
        den += __shfl_down_sync(0xffffffffu, den, o);
    }
    if ((threadIdx.x & 31) == 0) {
        atomicAdd(&g_num[r], num);
        atomicAdd(&g_den[r], den);
    }
}

// ---------------- final: mean of per-r ratios ----------------
__global__ void k_final(float* __restrict__ out) {
    int t = threadIdx.x;
    float v = (t < Rn) ? (g_num[t] / g_den[t]) : 0.0f;
    #pragma unroll
    for (int o = 16; o > 0; o >>= 1) v += __shfl_down_sync(0xffffffffu, v, o);
    if (t == 0) out[0] = v / (float)Rn;
}

// ---------------- launch ----------------
extern "C" void kernel_launch(void* const* d_in, const int* in_sizes, int n_in,
                              void* d_out, int out_size) {
    const float* x     = (const float*)d_in[0];
    const float* dten  = (const float*)d_in[1];
    const float* gts   = (const float*)d_in[2];
    const float* rnd   = (const float*)d_in[3];
    const float* Watt  = (const float*)d_in[4];
    const float* batt  = (const float*)d_in[5];
    const float* Wpost = (const float*)d_in[6];
    const float* bpost = (const float*)d_in[7];
    float* out = (float*)d_out;

    k_transpose_x<<<dim3(Ww/32, Hh, NB), dim3(32, 8)>>>(x);
    k_transpose_w<<<36, 256>>>(Watt, Wpost);
    k_pool<<<TOTPX/256, 256>>>(gts, rnd);
    k_zero<<<1, 32>>>();
    k_sample<<<TOTPX/8, 256>>>();
    k_conv1<<<dim3(ww/32, hh/8, Rn*NB), 256>>>(dten, batt);
    k_conv2<<<dim3(ww/32, (hh + 31)/32, Rn*NB), 128>>>(bpost);
    k_loss<<<Rn*32, 256>>>();
    k_final<<<1, 32>>>(out);
}

// round 3
// speedup vs baseline: 1.6334x; 1.6334x over previous
#include <cuda_runtime.h>
#include <cuda_bf16.h>
#include <cstdint>

// ---------------- problem constants ----------------
#define Rn     20
#define NB     4
#define Hh     480
#define Ww     640
#define hh     120
#define ww     160
#define FC     32
#define DC     32
#define NPIX   (hh*ww)           // 19200
#define NPIXH  (Hh*Ww)           // 307200
#define TOTPX  (Rn*NB*NPIX)      // 1,536,000
#define RB     (Rn*NB)           // 80
#define PADH   (hh+2)            // 122
#define PADW   (ww+2)            // 162
#define PADPIX (PADH*PADW)       // 19764
#define TOTPAD (RB*PADPIX)       // 1,581,120
#define TILES  155               // ceil(PADPIX/128)
#define STRIP  454               // 128 + 2*163 rows per tile
#define SPITCH 80                // smem row pitch (bytes) - bank-friendly
#define BIAS_I 1282
#define EPSF   1e-6f
#define BETAF  0.01f

// ---------------- device scratch ----------------
__device__ float        g_xT[(size_t)NB*Hh*Ww*FC];        // [b][y][x][c] fp32
__device__ uint32_t     g_bfrag1[18*4*32*2];              // conv1 B fragments
__device__ uint32_t     g_bfrag2[18*32*2];                // conv2 B fragments
__device__ float        g_rg[TOTPX];
__device__ float        g_cx[TOTPX];
__device__ float        g_cy[TOTPX];
__device__ __nv_bfloat16 g_featp[(size_t)RB*PADPIX*32];   // padded, channel-last
__device__ __nv_bfloat16 g_attdp[(size_t)RB*PADPIX*32];   // padded, channel-last
__device__ float        g_ds[(size_t)RB*4*NPIX];
__device__ float        g_num[Rn];
__device__ float        g_den[Rn];

// ---------------- helpers ----------------
__device__ __forceinline__ uint32_t smem_u32(const void* p) {
    uint32_t a;
    asm("{ .reg .u64 t; cvta.to.shared.u64 t, %1; cvt.u32.u64 %0, t; }"
        : "=r"(a) : "l"(p));
    return a;
}
__device__ __forceinline__ uint32_t pk2(float lo, float hi) {
    uint16_t l = __bfloat16_as_ushort(__float2bfloat16_rn(lo));
    uint16_t h = __bfloat16_as_ushort(__float2bfloat16_rn(hi));
    return (uint32_t)l | ((uint32_t)h << 16);
}

// ---------------- x transpose: [b][c][y][x] -> [b][y][x][c] ----------------
__global__ void k_transpose_x(const float* __restrict__ x) {
    __shared__ float tile[32][33];
    int b = blockIdx.z, y = blockIdx.y, x0 = blockIdx.x * 32;
    for (int c = threadIdx.y; c < 32; c += 8)
        tile[c][threadIdx.x] = x[(((size_t)b*32 + c)*Hh + y)*Ww + x0 + threadIdx.x];
    __syncthreads();
    for (int xx = threadIdx.y; xx < 32; xx += 8)
        g_xT[(((size_t)b*Hh + y)*Ww + x0 + xx)*32 + threadIdx.x] = tile[threadIdx.x][xx];
}

// ---------------- weight -> per-lane mma B fragments ----------------
// B (col-major k16 x n8): lane l: b0 = {B[k=(l%4)*2, n=l/4], B[k+1, n]}, b1 = k+8
__global__ void k_prep(const float* __restrict__ wa, const float* __restrict__ wp) {
    int e = blockIdx.x * 256 + threadIdx.x;
    if (e < 2304) {             // conv1: 18 kchunks x 4 ntiles x 32 lanes
        int lane = e & 31, nt = (e >> 5) & 3, kchunk = e >> 7;
        int tap = kchunk >> 1, kc = kchunk & 1;
        int ky = tap / 3, kx = tap % 3;
        int n  = nt * 8 + (lane >> 2);
        int ci = kc * 16 + (lane & 3) * 2;
        float w0 = wa[((n*32 + ci    )*3 + ky)*3 + kx];
        float w1 = wa[((n*32 + ci + 1)*3 + ky)*3 + kx];
        float w2 = wa[((n*32 + ci + 8)*3 + ky)*3 + kx];
        float w3 = wa[((n*32 + ci + 9)*3 + ky)*3 + kx];
        g_bfrag1[e*2 + 0] = pk2(w0, w1);
        g_bfrag1[e*2 + 1] = pk2(w2, w3);
    } else if (e < 2304 + 576) { // conv2: 18 kchunks x 32 lanes (1 ntile)
        int e2 = e - 2304;
        int lane = e2 & 31, kchunk = e2 >> 5;
        int tap = kchunk >> 1, kc = kchunk & 1;
        int ky = tap / 3, kx = tap % 3;
        int n  = lane >> 2;
        int ci = kc * 16 + (lane & 3) * 2;
        float w0 = 0.f, w1 = 0.f, w2 = 0.f, w3 = 0.f;
        if (n < 4) {
            w0 = wp[((n*32 + ci    )*3 + ky)*3 + kx];
            w1 = wp[((n*32 + ci + 1)*3 + ky)*3 + kx];
            w2 = wp[((n*32 + ci + 8)*3 + ky)*3 + kx];
            w3 = wp[((n*32 + ci + 9)*3 + ky)*3 + kx];
        }
        g_bfrag2[e2*2 + 0] = pk2(w0, w1);
        g_bfrag2[e2*2 + 1] = pk2(w2, w3);
    }
}

// ---------------- random pooling + coordinate maps ----------------
__global__ void k_pool(const float* __restrict__ gts, const float* __restrict__ rnd) {
    int tid = blockIdx.x * 256 + threadIdx.x;
    if (tid >= TOTPX) return;
    int ox = tid % ww; int t2 = tid / ww;
    int oy = t2 % hh;  t2 /= hh;
    int b  = t2 % NB;  int r = t2 / NB;
    const float* rp = rnd + (size_t)(r*NB + b) * NPIXH;
    const float* gp = gts + (size_t)b * NPIXH;
    int gy0 = oy * 4, gx0 = ox * 4;
    float best = -1.0f; int bi = 0, bj = 0;
    #pragma unroll
    for (int i = 0; i < 4; i++) {
        const float4 rv = *(const float4*)(rp + (size_t)(gy0 + i)*Ww + gx0);
        const float4 gv = *(const float4*)(gp + (size_t)(gy0 + i)*Ww + gx0);
        float rr[4] = {rv.x, rv.y, rv.z, rv.w};
        float gg[4] = {gv.x, gv.y, gv.z, gv.w};
        #pragma unroll
        for (int j = 0; j < 4; j++) {
            float m = (gg[j] > 0.1f) ? rr[j] : 0.0f;
            if (m > best) { best = m; bi = i; bj = j; }
        }
    }
    int row = gy0 + bi, col = gx0 + bj;
    float g = gp[(size_t)row*Ww + col];
    g_rg[tid] = (g < 0.1f) ? 0.0f : g;
    int idx = row * Ww + col + BIAS_I;
    int qy = idx / Ww; int qx = idx - qy * Ww;
    g_cx[tid] = ((float)qx / (float)Ww) * (float)(Ww - 1);
    g_cy[tid] = ((float)qy / (float)Hh) * (float)(Hh - 1);
}

// ---------------- bilinear gather into padded bf16 channel-last ------------
__global__ void k_samplep() {
    int gid  = blockIdx.x * 256 + threadIdx.x;
    int wid  = gid >> 5;
    int lane = threadIdx.x & 31;
    if (wid >= TOTPAD) return;
    int p  = wid % PADPIX;
    int rb = wid / PADPIX;
    int py = p / PADW, px = p - py * PADW;
    float acc = 0.0f;
    if (py >= 1 && py <= hh && px >= 1 && px <= ww) {
        int tid = rb * NPIX + (py - 1) * ww + (px - 1);
        float cx = g_cx[tid], cy = g_cy[tid];
        float fx = floorf(cx), fy = floorf(cy);
        int x0 = (int)fx, y0 = (int)fy;
        float wx = cx - fx, wy = cy - fy;
        int b = rb & 3;
        const float* base = g_xT + (size_t)b * Hh * Ww * 32 + lane;
        float w00 = (1.f - wx) * (1.f - wy), w10 = wx * (1.f - wy);
        float w01 = (1.f - wx) * wy,         w11 = wx * wy;
        bool vy0 = (y0 >= 0) && (y0 <= Hh - 1);
        bool vy1 = (y0 + 1 >= 0) && (y0 + 1 <= Hh - 1);
        bool vx0 = (x0 >= 0) && (x0 <= Ww - 1);
        bool vx1 = (x0 + 1 >= 0) && (x0 + 1 <= Ww - 1);
        if (vy0) {
            if (vx0) acc += w00 * base[((size_t)y0*Ww + x0)*32];
            if (vx1) acc += w10 * base[((size_t)y0*Ww + x0 + 1)*32];
        }
        if (vy1) {
            if (vx0) acc += w01 * base[((size_t)(y0+1)*Ww + x0)*32];
            if (vx1) acc += w11 * base[((size_t)(y0+1)*Ww + x0 + 1)*32];
        }
    }
    // pack channel pairs -> bf16x2, lanes 0..15 store
    float v0 = __shfl_sync(0xffffffffu, acc, (lane*2) & 31);
    float v1 = __shfl_sync(0xffffffffu, acc, (lane*2+1) & 31);
    if (lane < 16)
        *reinterpret_cast<uint32_t*>(&g_featp[(size_t)wid*32 + lane*2]) = pk2(v0, v1);
}

// ---------------- zero attdp (padding border must be zero) ----------------
__global__ void k_zero_attdp() {
    size_t i = (size_t)blockIdx.x * 256 + threadIdx.x;
    if (i < (size_t)TOTPAD * 4)
        reinterpret_cast<uint4*>(g_attdp)[i] = make_uint4(0,0,0,0);
}

// ---------------- conv1: 9-tap bf16 MMA GEMM + sigmoid*d -> attdp ---------
// block: 256 thr (8 warps), M=128 flat-padded pixels, N=32, K=288
__global__ void __launch_bounds__(256) k_conv1mma(const float* __restrict__ dten,
                                                  const float* __restrict__ batt) {
    extern __shared__ unsigned char smem[];
    unsigned char* s_strip = smem;                       // STRIP*SPITCH = 36320
    uint32_t* s_bf = (uint32_t*)(smem + STRIP*SPITCH);   // 4608 u32 = 18432
    int rb = blockIdx.y, tile = blockIdx.x;
    int p0 = tile * 128, base = p0 - 163;
    int t = threadIdx.x;
    const unsigned char* fp = (const unsigned char*)(g_featp + (size_t)rb * PADPIX * 32);

    for (int e = t; e < 4608; e += 256) s_bf[e] = g_bfrag1[e];
    for (int e = t; e < STRIP*4; e += 256) {
        int r = e >> 2, j = e & 3;
        int gr = base + r;
        uint4 v = make_uint4(0,0,0,0);
        if (gr >= 0 && gr < PADPIX)
            v = *(const uint4*)(fp + (size_t)gr*64 + j*16);
        *(uint4*)(s_strip + r*SPITCH + j*16) = v;
    }
    __syncthreads();

    int warp = t >> 5, lane = t & 31;
    float acc[4][4] = {};
    uint32_t arow = smem_u32(s_strip) + (warp*16 + (lane & 15))*SPITCH + (lane >> 4)*16;

    #pragma unroll
    for (int tap = 0; tap < 9; tap++) {
        int tl = (tap/3)*PADW + (tap%3);
        #pragma unroll
        for (int kc = 0; kc < 2; kc++) {
            uint32_t a0,a1,a2,a3;
            uint32_t addr = arow + tl*SPITCH + kc*32;
            asm volatile("ldmatrix.sync.aligned.m8n8.x4.shared.b16 {%0,%1,%2,%3}, [%4];"
                : "=r"(a0),"=r"(a1),"=r"(a2),"=r"(a3) : "r"(addr));
            int kchunk = tap*2 + kc;
            #pragma unroll
            for (int nt = 0; nt < 4; nt++) {
                uint32_t b0 = s_bf[kchunk*256 + nt*64 + lane*2];
                uint32_t b1 = s_bf[kchunk*256 + nt*64 + lane*2 + 1];
                asm volatile("mma.sync.aligned.m16n8k16.row.col.f32.bf16.bf16.f32 "
                    "{%0,%1,%2,%3}, {%4,%5,%6,%7}, {%8,%9}, {%0,%1,%2,%3};"
                    : "+f"(acc[nt][0]),"+f"(acc[nt][1]),"+f"(acc[nt][2]),"+f"(acc[nt][3])
                    : "r"(a0),"r"(a1),"r"(a2),"r"(a3),"r"(b0),"r"(b1));
            }
        }
    }
    // epilogue: bias -> sigmoid -> * d -> attdp (bf16 padded channel-last)
    int b = rb & 3;
    int colb = (lane & 3) * 2;
    #pragma unroll
    for (int rr = 0; rr < 2; rr++) {
        int m = warp*16 + (lane >> 2) + rr*8;
        int p = p0 + m;
        int py = p / PADW, px = p - py*PADW;
        if (py >= 1 && py <= hh && px >= 1 && px <= ww) {
            int y = py - 1, x = px - 1;
            __nv_bfloat16* op = g_attdp + ((size_t)rb*PADPIX + p)*32;
            #pragma unroll
            for (int nt = 0; nt < 4; nt++) {
                float o0 = 0.f, o1 = 0.f;
                #pragma unroll
                for (int cc = 0; cc < 2; cc++) {
                    int co = nt*8 + colb + cc;
                    float v = acc[nt][rr*2 + cc] + batt[co];
                    float att = 1.0f / (1.0f + __expf(-v));
                    float dv = dten[(((size_t)b*DC + co)*hh + y)*ww + x];
                    if (cc == 0) o0 = att * dv; else o1 = att * dv;
                }
                *reinterpret_cast<uint32_t*>(op + nt*8 + colb) = pk2(o0, o1);
            }
        }
    }
}

// ---------------- conv2: 9-tap bf16 MMA, N=8 (4 real) -> ds fp32 ----------
__global__ void __launch_bounds__(256) k_conv2mma(const float* __restrict__ bpost) {
    __shared__ __align__(16) unsigned char s_strip[STRIP*SPITCH];
    __shared__ uint32_t s_bf[1152];
    int rb = blockIdx.y, tile = blockIdx.x;
    int p0 = tile * 128, base = p0 - 163;
    int t = threadIdx.x;
    const unsigned char* ap = (const unsigned char*)(g_attdp + (size_t)rb * PADPIX * 32);

    for (int e = t; e < 1152; e += 256) s_bf[e] = g_bfrag2[e];
    for (int e = t; e < STRIP*4; e += 256) {
        int r = e >> 2, j = e & 3;
        int gr = base + r;
        uint4 v = make_uint4(0,0,0,0);
        if (gr >= 0 && gr < PADPIX)
            v = *(const uint4*)(ap + (size_t)gr*64 + j*16);
        *(uint4*)(s_strip + r*SPITCH + j*16) = v;
    }
    __syncthreads();

    int warp = t >> 5, lane = t & 31;
    float acc[4] = {};
    uint32_t arow = smem_u32(s_strip) + (warp*16 + (lane & 15))*SPITCH + (lane >> 4)*16;

    #pragma unroll
    for (int tap = 0; tap < 9; tap++) {
        int tl = (tap/3)*PADW + (tap%3);
        #pragma unroll
        for (int kc = 0; kc < 2; kc++) {
            uint32_t a0,a1,a2,a3;
            uint32_t addr = arow + tl*SPITCH + kc*32;
            asm volatile("ldmatrix.sync.aligned.m8n8.x4.shared.b16 {%0,%1,%2,%3}, [%4];"
                : "=r"(a0),"=r"(a1),"=r"(a2),"=r"(a3) : "r"(addr));
            int kchunk = tap*2 + kc;
            uint32_t b0 = s_bf[kchunk*64 + lane*2];
            uint32_t b1 = s_bf[kchunk*64 + lane*2 + 1];
            asm volatile("mma.sync.aligned.m16n8k16.row.col.f32.bf16.bf16.f32 "
                "{%0,%1,%2,%3}, {%4,%5,%6,%7}, {%8,%9}, {%0,%1,%2,%3};"
                : "+f"(acc[0]),"+f"(acc[1]),"+f"(acc[2]),"+f"(acc[3])
                : "r"(a0),"r"(a1),"r"(a2),"r"(a3),"r"(b0),"r"(b1));
        }
    }
    int colb = (lane & 3) * 2;
    #pragma unroll
    for (int rr = 0; rr < 2; rr++) {
        int m = warp*16 + (lane >> 2) + rr*8;
        int p = p0 + m;
        int py = p / PADW, px = p - py*PADW;
        if (py >= 1 && py <= hh && px >= 1 && px <= ww) {
            int y = py - 1, x = px - 1;
            #pragma unroll
            for (int cc = 0; cc < 2; cc++) {
                int co = colb + cc;
                if (co < 4)
                    g_ds[((size_t)rb*4 + co)*NPIX + y*ww + x] = acc[rr*2 + cc] + bpost[co];
            }
        }
    }
}

// ---------------- zero accumulators ----------------
__global__ void k_zero() {
    int t = threadIdx.x;
    if (t < Rn) { g_num[t] = 0.0f; g_den[t] = 0.0f; }
}

// ---------------- log-grad + smooth L1 + reduce ----------------
__global__ void k_loss() {
    int r = blockIdx.x >> 5;
    int chunk = blockIdx.x & 31;
    float num = 0.0f, den = 0.0f;
    const int dy[4] = {0, 1, 1, 1};
    const int dx[4] = {1, 1, 0, -1};
    for (int j = chunk*2400 + threadIdx.x; j < (chunk + 1)*2400; j += 256) {
        int b = j / NPIX; int p = j - b * NPIX;
        int y = p / ww, x = p - y * ww;
        const float* rgp = g_rg + (size_t)(r*NB + b) * NPIX;
        float c = rgp[p];
        if (c > 0.1f) {
            float logc = __logf(c + EPSF);
            const float* dsp = g_ds + (size_t)(r*NB + b) * 4 * NPIX + p;
            #pragma unroll
            for (int k = 0; k < 4; k++) {
                int yn = y + dy[k], xn = x + dx[k];
                if (yn < hh && xn >= 0 && xn < ww) {
                    float nb = rgp[yn*ww + xn];
                    if (nb > 0.1f) {
                        float grad = logc - __logf(nb + EPSF);
                        float a = fabsf(dsp[k*NPIX] - grad);
                        float s = (a < BETAF) ? (0.5f/BETAF)*a*a : a - 0.5f*BETAF;
                        num += s; den += 1.0f;
                    }
                }
            }
        }
    }
    #pragma unroll
    for (int o = 16; o > 0; o >>= 1) {
        num += __shfl_down_sync(0xffffffffu, num, o);
        den += __shfl_down_sync(0xffffffffu, den, o);
    }
    if ((threadIdx.x & 31) == 0) {
        atomicAdd(&g_num[r], num);
        atomicAdd(&g_den[r], den);
    }
}

// ---------------- final: mean of per-r ratios ----------------
__global__ void k_final(float* __restrict__ out) {
    int t = threadIdx.x;
    float v = (t < Rn) ? (g_num[t] / g_den[t]) : 0.0f;
    #pragma unroll
    for (int o = 16; o > 0; o >>= 1) v += __shfl_down_sync(0xffffffffu, v, o);
    if (t == 0) out[0] = v / (float)Rn;
}

// ---------------- launch ----------------
extern "C" void kernel_launch(void* const* d_in, const int* in_sizes, int n_in,
                              void* d_out, int out_size) {
    const float* x     = (const float*)d_in[0];
    const float* dten  = (const float*)d_in[1];
    const float* gts   = (const float*)d_in[2];
    const float* rnd   = (const float*)d_in[3];
    const float* Watt  = (const float*)d_in[4];
    const float* batt  = (const float*)d_in[5];
    const float* Wpost = (const float*)d_in[6];
    const float* bpost = (const float*)d_in[7];
    float* out = (float*)d_out;

    cudaFuncSetAttribute(k_conv1mma, cudaFuncAttributeMaxDynamicSharedMemorySize,
                         STRIP*SPITCH + 4608*4);

    k_transpose_x<<<dim3(Ww/32, Hh, NB), dim3(32, 8)>>>(x);
    k_prep<<<12, 256>>>(Watt, Wpost);
    k_pool<<<TOTPX/256, 256>>>(gts, rnd);
    k_zero<<<1, 32>>>();
    k_zero_attdp<<<(TOTPAD*4 + 255)/256, 256>>>();
    {
        long long tp = (long long)TOTPAD * 32;
        k_samplep<<<(unsigned)((tp + 255)/256), 256>>>();
    }
    k_conv1mma<<<dim3(TILES, RB), 256, STRIP*SPITCH + 4608*4>>>(dten, batt);
    k_conv2mma<<<dim3(TILES, RB), 256>>>(bpost);
    k_loss<<<Rn*32, 256>>>();
    k_final<<<1, 32>>>(out);
}

// round 4
// speedup vs baseline: 1.7520x; 1.0727x over previous
#include <cuda_runtime.h>
#include <cuda_bf16.h>
#include <cstdint>

// ---------------- problem constants ----------------
#define Rn     20
#define NB     4
#define Hh     480
#define Ww     640
#define hh     120
#define ww     160
#define FC     32
#define DC     32
#define NPIX   (hh*ww)           // 19200
#define NPIXH  (Hh*Ww)           // 307200
#define TOTPX  (Rn*NB*NPIX)      // 1,536,000
#define RB     (Rn*NB)           // 80
#define PADH   (hh+2)            // 122
#define PADW   (ww+2)            // 162
#define PADPIX (PADH*PADW)       // 19764
#define TOTPAD (RB*PADPIX)       // 1,581,120
#define MTILE  512
#define TILES1 39                // ceil(PADPIX/512)
#define STRIP1 838               // 512 + 2*163
#define SPITCH 80                // smem row pitch (bytes)
#define BIAS_I 1282
#define EPSF   1e-6f
#define BETAF  0.01f

// ---------------- device scratch ----------------
__device__ __nv_bfloat16 g_xTb[(size_t)NB*Hh*Ww*FC];      // [b][y][x][c] bf16
__device__ uint32_t     g_bfrag1[18*4*32*2];              // conv1 B fragments
__device__ uint32_t     g_bfrag2[18*32*2];                // conv2 B fragments
__device__ float        g_rg[TOTPX];
__device__ float        g_cx[TOTPX];
__device__ float        g_cy[TOTPX];
__device__ __nv_bfloat16 g_featp[(size_t)RB*PADPIX*32];   // padded, channel-last
__device__ __nv_bfloat16 g_attdp[(size_t)RB*PADPIX*32];   // padded, channel-last
__device__ float        g_num[Rn];
__device__ float        g_den[Rn];

// ---------------- helpers ----------------
__device__ __forceinline__ uint32_t smem_u32(const void* p) {
    uint32_t a;
    asm("{ .reg .u64 t; cvta.to.shared.u64 t, %1; cvt.u32.u64 %0, t; }"
        : "=r"(a) : "l"(p));
    return a;
}
__device__ __forceinline__ uint32_t pk2(float lo, float hi) {
    uint16_t l = __bfloat16_as_ushort(__float2bfloat16_rn(lo));
    uint16_t h = __bfloat16_as_ushort(__float2bfloat16_rn(hi));
    return (uint32_t)l | ((uint32_t)h << 16);
}

// ---------------- x transpose: [b][c][y][x] -> [b][y][x][c] bf16 -----------
__global__ void k_transpose_x(const float* __restrict__ x) {
    __shared__ float tile[32][33];
    int b = blockIdx.z, y = blockIdx.y, x0 = blockIdx.x * 32;
    for (int c = threadIdx.y; c < 32; c += 8)
        tile[c][threadIdx.x] = x[(((size_t)b*32 + c)*Hh + y)*Ww + x0 + threadIdx.x];
    __syncthreads();
    for (int xx = threadIdx.y; xx < 32; xx += 8)
        g_xTb[(((size_t)b*Hh + y)*Ww + x0 + xx)*32 + threadIdx.x] =
            __float2bfloat16_rn(tile[threadIdx.x][xx]);
}

// ---------------- weight -> per-lane mma B fragments (+ zero accums) -------
__global__ void k_prep(const float* __restrict__ wa, const float* __restrict__ wp) {
    int e = blockIdx.x * 256 + threadIdx.x;
    if (e < 2304) {             // conv1: 18 kchunks x 4 ntiles x 32 lanes
        int lane = e & 31, nt = (e >> 5) & 3, kchunk = e >> 7;
        int tap = kchunk >> 1, kc = kchunk & 1;
        int ky = tap / 3, kx = tap % 3;
        int n  = nt * 8 + (lane >> 2);
        int ci = kc * 16 + (lane & 3) * 2;
        float w0 = wa[((n*32 + ci    )*3 + ky)*3 + kx];
        float w1 = wa[((n*32 + ci + 1)*3 + ky)*3 + kx];
        float w2 = wa[((n*32 + ci + 8)*3 + ky)*3 + kx];
        float w3 = wa[((n*32 + ci + 9)*3 + ky)*3 + kx];
        g_bfrag1[e*2 + 0] = pk2(w0, w1);
        g_bfrag1[e*2 + 1] = pk2(w2, w3);
    } else if (e < 2880) {      // conv2: 18 kchunks x 32 lanes
        int e2 = e - 2304;
        int lane = e2 & 31, kchunk = e2 >> 5;
        int tap = kchunk >> 1, kc = kchunk & 1;
        int ky = tap / 3, kx = tap % 3;
        int n  = lane >> 2;
        int ci = kc * 16 + (lane & 3) * 2;
        float w0 = 0.f, w1 = 0.f, w2 = 0.f, w3 = 0.f;
        if (n < 4) {
            w0 = wp[((n*32 + ci    )*3 + ky)*3 + kx];
            w1 = wp[((n*32 + ci + 1)*3 + ky)*3 + kx];
            w2 = wp[((n*32 + ci + 8)*3 + ky)*3 + kx];
            w3 = wp[((n*32 + ci + 9)*3 + ky)*3 + kx];
        }
        g_bfrag2[e2*2 + 0] = pk2(w0, w1);
        g_bfrag2[e2*2 + 1] = pk2(w2, w3);
    } else if (e < 2880 + Rn) {
        g_num[e - 2880] = 0.0f;
        g_den[e - 2880] = 0.0f;
    }
}

// ---------------- random pooling + coordinate maps ----------------
__global__ void k_pool(const float* __restrict__ gts, const float* __restrict__ rnd) {
    int tid = blockIdx.x * 256 + threadIdx.x;
    if (tid >= TOTPX) return;
    int ox = tid % ww; int t2 = tid / ww;
    int oy = t2 % hh;  t2 /= hh;
    int b  = t2 % NB;  int r = t2 / NB;
    const float* rp = rnd + (size_t)(r*NB + b) * NPIXH;
    const float* gp = gts + (size_t)b * NPIXH;
    int gy0 = oy * 4, gx0 = ox * 4;
    float best = -1.0f; int bi = 0, bj = 0;
    #pragma unroll
    for (int i = 0; i < 4; i++) {
        const float4 rv = *(const float4*)(rp + (size_t)(gy0 + i)*Ww + gx0);
        const float4 gv = *(const float4*)(gp + (size_t)(gy0 + i)*Ww + gx0);
        float rr[4] = {rv.x, rv.y, rv.z, rv.w};
        float gg[4] = {gv.x, gv.y, gv.z, gv.w};
        #pragma unroll
        for (int j = 0; j < 4; j++) {
            float m = (gg[j] > 0.1f) ? rr[j] : 0.0f;
            if (m > best) { best = m; bi = i; bj = j; }
        }
    }
    int row = gy0 + bi, col = gx0 + bj;
    float g = gp[(size_t)row*Ww + col];
    g_rg[tid] = (g < 0.1f) ? 0.0f : g;
    int idx = row * Ww + col + BIAS_I;
    int qy = idx / Ww; int qx = idx - qy * Ww;
    g_cx[tid] = ((float)qx / (float)Ww) * (float)(Ww - 1);
    g_cy[tid] = ((float)qy / (float)Hh) * (float)(Hh - 1);
}

// ---------------- bilinear gather into padded bf16 channel-last ------------
__global__ void k_samplep() {
    int gid  = blockIdx.x * 256 + threadIdx.x;
    int wid  = gid >> 5;
    int lane = threadIdx.x & 31;
    if (wid >= TOTPAD) return;
    int p  = wid % PADPIX;
    int rb = wid / PADPIX;
    int py = p / PADW, px = p - py * PADW;
    float acc = 0.0f;
    if (py >= 1 && py <= hh && px >= 1 && px <= ww) {
        int tid = rb * NPIX + (py - 1) * ww + (px - 1);
        float cx = g_cx[tid], cy = g_cy[tid];
        float fx = floorf(cx), fy = floorf(cy);
        int x0 = (int)fx, y0 = (int)fy;
        float wx = cx - fx, wy = cy - fy;
        int b = rb & 3;
        const __nv_bfloat16* base = g_xTb + (size_t)b * Hh * Ww * 32 + lane;
        float w00 = (1.f - wx) * (1.f - wy), w10 = wx * (1.f - wy);
        float w01 = (1.f - wx) * wy,         w11 = wx * wy;
        bool vy0 = (y0 >= 0) && (y0 <= Hh - 1);
        bool vy1 = (y0 + 1 >= 0) && (y0 + 1 <= Hh - 1);
        bool vx0 = (x0 >= 0) && (x0 <= Ww - 1);
        bool vx1 = (x0 + 1 >= 0) && (x0 + 1 <= Ww - 1);
        if (vy0) {
            if (vx0) acc += w00 * __bfloat162float(base[((size_t)y0*Ww + x0)*32]);
            if (vx1) acc += w10 * __bfloat162float(base[((size_t)y0*Ww + x0 + 1)*32]);
        }
        if (vy1) {
            if (vx0) acc += w01 * __bfloat162float(base[((size_t)(y0+1)*Ww + x0)*32]);
            if (vx1) acc += w11 * __bfloat162float(base[((size_t)(y0+1)*Ww + x0 + 1)*32]);
        }
    }
    float v0 = __shfl_sync(0xffffffffu, acc, (lane*2) & 31);
    float v1 = __shfl_sync(0xffffffffu, acc, (lane*2+1) & 31);
    if (lane < 16)
        *reinterpret_cast<uint32_t*>(&g_featp[(size_t)wid*32 + lane*2]) = pk2(v0, v1);
}

// ---------------- conv1: 9-tap bf16 MMA, M=512, + sigmoid*d -> attdp ------
// block: 256 thr (8 warps), each warp 64 flat pixels (4 m-subtiles of 16)
__global__ void __launch_bounds__(256, 2) k_conv1mma(const float* __restrict__ dten,
                                                     const float* __restrict__ batt) {
    extern __shared__ unsigned char smem[];
    unsigned char* s_strip = smem;                       // STRIP1*SPITCH = 67040
    uint32_t* s_bf = (uint32_t*)(smem + STRIP1*SPITCH);  // 4608 u32 = 18432
    int rb = blockIdx.y, tile = blockIdx.x;
    int p0 = tile * MTILE, base = p0 - 163;
    int t = threadIdx.x;
    const unsigned char* fp = (const unsigned char*)(g_featp + (size_t)rb * PADPIX * 32);

    for (int e = t; e < 4608; e += 256) s_bf[e] = g_bfrag1[e];
    for (int e = t; e < STRIP1*4; e += 256) {
        int r = e >> 2, j = e & 3;
        int gr = base + r;
        uint4 v = make_uint4(0,0,0,0);
        if (gr >= 0 && gr < PADPIX)
            v = *(const uint4*)(fp + (size_t)gr*64 + j*16);
        *(uint4*)(s_strip + r*SPITCH + j*16) = v;
    }
    __syncthreads();

    int warp = t >> 5, lane = t & 31;
    float acc[4][4][4] = {};
    uint32_t arow = smem_u32(s_strip) + (warp*64 + (lane & 15))*SPITCH + (lane >> 4)*16;

    #pragma unroll
    for (int tap = 0; tap < 9; tap++) {
        int tl = (tap/3)*PADW + (tap%3);
        #pragma unroll
        for (int kc = 0; kc < 2; kc++) {
            int kchunk = tap*2 + kc;
            uint32_t b0[4], b1[4];
            #pragma unroll
            for (int nt = 0; nt < 4; nt++) {
                b0[nt] = s_bf[kchunk*256 + nt*64 + lane*2];
                b1[nt] = s_bf[kchunk*256 + nt*64 + lane*2 + 1];
            }
            #pragma unroll
            for (int ms = 0; ms < 4; ms++) {
                uint32_t a0,a1,a2,a3;
                uint32_t addr = arow + (ms*16 + tl)*SPITCH + kc*32;
                asm volatile("ldmatrix.sync.aligned.m8n8.x4.shared.b16 {%0,%1,%2,%3}, [%4];"
                    : "=r"(a0),"=r"(a1),"=r"(a2),"=r"(a3) : "r"(addr));
                #pragma unroll
                for (int nt = 0; nt < 4; nt++) {
                    asm volatile("mma.sync.aligned.m16n8k16.row.col.f32.bf16.bf16.f32 "
                        "{%0,%1,%2,%3}, {%4,%5,%6,%7}, {%8,%9}, {%0,%1,%2,%3};"
                        : "+f"(acc[ms][nt][0]),"+f"(acc[ms][nt][1]),
                          "+f"(acc[ms][nt][2]),"+f"(acc[ms][nt][3])
                        : "r"(a0),"r"(a1),"r"(a2),"r"(a3),"r"(b0[nt]),"r"(b1[nt]));
                }
            }
        }
    }
    // epilogue: bias -> sigmoid -> * d -> attdp; borders get zeros
    int b = rb & 3;
    int colb = (lane & 3) * 2;
    #pragma unroll
    for (int ms = 0; ms < 4; ms++) {
        #pragma unroll
        for (int rr = 0; rr < 2; rr++) {
            int m = warp*64 + ms*16 + (lane >> 2) + rr*8;
            int p = p0 + m;
            if (p >= PADPIX) continue;
            int py = p / PADW, px = p - py*PADW;
            __nv_bfloat16* op = g_attdp + ((size_t)rb*PADPIX + p)*32;
            if (py >= 1 && py <= hh && px >= 1 && px <= ww) {
                int y = py - 1, x = px - 1;
                #pragma unroll
                for (int nt = 0; nt < 4; nt++) {
                    int co0 = nt*8 + colb;
                    float v0 = acc[ms][nt][rr*2]     + batt[co0];
                    float v1 = acc[ms][nt][rr*2 + 1] + batt[co0 + 1];
                    float at0 = 1.0f / (1.0f + __expf(-v0));
                    float at1 = 1.0f / (1.0f + __expf(-v1));
                    float d0 = dten[(((size_t)b*DC + co0    )*hh + y)*ww + x];
                    float d1 = dten[(((size_t)b*DC + co0 + 1)*hh + y)*ww + x];
                    *reinterpret_cast<uint32_t*>(op + co0) = pk2(at0*d0, at1*d1);
                }
            } else {
                #pragma unroll
                for (int nt = 0; nt < 4; nt++)
                    *reinterpret_cast<uint32_t*>(op + nt*8 + colb) = 0u;
            }
        }
    }
}

// ---------------- conv2: 9-tap bf16 MMA, M=512, N=8(4 real) + fused loss ---
__global__ void __launch_bounds__(256, 2) k_conv2loss(const float* __restrict__ bpost) {
    extern __shared__ unsigned char smem[];
    unsigned char* s_strip = smem;                       // STRIP1*SPITCH
    uint32_t* s_bf = (uint32_t*)(smem + STRIP1*SPITCH);  // 1152 u32
    int rb = blockIdx.y, tile = blockIdx.x;
    int p0 = tile * MTILE, base = p0 - 163;
    int t = threadIdx.x;
    const unsigned char* ap = (const unsigned char*)(g_attdp + (size_t)rb * PADPIX * 32);

    for (int e = t; e < 1152; e += 256) s_bf[e] = g_bfrag2[e];
    for (int e = t; e < STRIP1*4; e += 256) {
        int r = e >> 2, j = e & 3;
        int gr = base + r;
        uint4 v = make_uint4(0,0,0,0);
        if (gr >= 0 && gr < PADPIX)
            v = *(const uint4*)(ap + (size_t)gr*64 + j*16);
        *(uint4*)(s_strip + r*SPITCH + j*16) = v;
    }
    __syncthreads();

    int warp = t >> 5, lane = t & 31;
    float acc[4][4] = {};
    uint32_t arow = smem_u32(s_strip) + (warp*64 + (lane & 15))*SPITCH + (lane >> 4)*16;

    #pragma unroll
    for (int tap = 0; tap < 9; tap++) {
        int tl = (tap/3)*PADW + (tap%3);
        #pragma unroll
        for (int kc = 0; kc < 2; kc++) {
            int kchunk = tap*2 + kc;
            uint32_t b0 = s_bf[kchunk*64 + lane*2];
            uint32_t b1 = s_bf[kchunk*64 + lane*2 + 1];
            #pragma unroll
            for (int ms = 0; ms < 4; ms++) {
                uint32_t a0,a1,a2,a3;
                uint32_t addr = arow + (ms*16 + tl)*SPITCH + kc*32;
                asm volatile("ldmatrix.sync.aligned.m8n8.x4.shared.b16 {%0,%1,%2,%3}, [%4];"
                    : "=r"(a0),"=r"(a1),"=r"(a2),"=r"(a3) : "r"(addr));
                asm volatile("mma.sync.aligned.m16n8k16.row.col.f32.bf16.bf16.f32 "
                    "{%0,%1,%2,%3}, {%4,%5,%6,%7}, {%8,%9}, {%0,%1,%2,%3};"
                    : "+f"(acc[ms][0]),"+f"(acc[ms][1]),"+f"(acc[ms][2]),"+f"(acc[ms][3])
                    : "r"(a0),"r"(a1),"r"(a2),"r"(a3),"r"(b0),"r"(b1));
            }
        }
    }

    // fused loss epilogue: ds = acc + bias; smooth-L1 against log-grads of rg
    const int dyk[4] = {0, 1, 1, 1};
    const int dxk[4] = {1, 1, 0, -1};
    float num = 0.0f, den = 0.0f;
    int colb = (lane & 3) * 2;   // co pair; only colb<4 contributes
    const float* rgp = g_rg + (size_t)rb * NPIX;
    if (colb < 4) {
        float bb0 = bpost[colb], bb1 = bpost[colb + 1];
        #pragma unroll
        for (int ms = 0; ms < 4; ms++) {
            #pragma unroll
            for (int rr = 0; rr < 2; rr++) {
                int m = warp*64 + ms*16 + (lane >> 2) + rr*8;
                int p = p0 + m;
                if (p >= PADPIX) continue;
                int py = p / PADW, px = p - py*PADW;
                if (py < 1 || py > hh || px < 1 || px > ww) continue;
                int y = py - 1, x = px - 1;
                float c = rgp[y*ww + x];
                if (c <= 0.1f) continue;
                float logc = __logf(c + EPSF);
                float ds[2] = { acc[ms][rr*2] + bb0, acc[ms][rr*2 + 1] + bb1 };
                #pragma unroll
                for (int cc = 0; cc < 2; cc++) {
                    int k = colb + cc;
                    int yn = y + dyk[k], xn = x + dxk[k];
                    if (yn < hh && xn >= 0 && xn < ww) {
                        float nb = rgp[yn*ww + xn];
                        if (nb > 0.1f) {
                            float grad = logc - __logf(nb + EPSF);
                            float a = fabsf(ds[cc] - grad);
                            float s = (a < BETAF) ? (0.5f/BETAF)*a*a : a - 0.5f*BETAF;
                            num += s; den += 1.0f;
                        }
                    }
                }
            }
        }
    }
    #pragma unroll
    for (int o = 16; o > 0; o >>= 1) {
        num += __shfl_down_sync(0xffffffffu, num, o);
        den += __shfl_down_sync(0xffffffffu, den, o);
    }
    if (lane == 0 && (num != 0.0f || den != 0.0f)) {
        int r = rb >> 2;
        atomicAdd(&g_num[r], num);
        atomicAdd(&g_den[r], den);
    }
}

// ---------------- final: mean of per-r ratios ----------------
__global__ void k_final(float* __restrict__ out) {
    int t = threadIdx.x;
    float v = (t < Rn) ? (g_num[t] / g_den[t]) : 0.0f;
    #pragma unroll
    for (int o = 16; o > 0; o >>= 1) v += __shfl_down_sync(0xffffffffu, v, o);
    if (t == 0) out[0] = v / (float)Rn;
}

// ---------------- launch ----------------
extern "C" void kernel_launch(void* const* d_in, const int* in_sizes, int n_in,
                              void* d_out, int out_size) {
    const float* x     = (const float*)d_in[0];
    const float* dten  = (const float*)d_in[1];
    const float* gts   = (const float*)d_in[2];
    const float* rnd   = (const float*)d_in[3];
    const float* Watt  = (const float*)d_in[4];
    const float* Wpost = (const float*)d_in[6];
    const float* bpost = (const float*)d_in[7];
    const float* batt  = (const float*)d_in[5];
    float* out = (float*)d_out;

    static int attr_done = 0;
    if (!attr_done) {
        cudaFuncSetAttribute(k_conv1mma, cudaFuncAttributeMaxDynamicSharedMemorySize,
                             STRIP1*SPITCH + 4608*4);
        cudaFuncSetAttribute(k_conv2loss, cudaFuncAttributeMaxDynamicSharedMemorySize,
                             STRIP1*SPITCH + 1152*4);
        attr_done = 1;
    }

    k_transpose_x<<<dim3(Ww/32, Hh, NB), dim3(32, 8)>>>(x);
    k_prep<<<12, 256>>>(Watt, Wpost);
    k_pool<<<TOTPX/256, 256>>>(gts, rnd);
    {
        long long tp = (long long)TOTPAD * 32;
        k_samplep<<<(unsigned)((tp + 255)/256), 256>>>();
    }
    k_conv1mma<<<dim3(TILES1, RB), 256, STRIP1*SPITCH + 4608*4>>>(dten, batt);
    k_conv2loss<<<dim3(TILES1, RB), 256, STRIP1*SPITCH + 1152*4>>>(bpost);
    k_final<<<1, 32>>>(out);
}

// round 5
// speedup vs baseline: 2.3722x; 1.3540x over previous
#include <cuda_runtime.h>
#include <cuda_bf16.h>
#include <cstdint>

// ---------------- problem constants ----------------
#define Rn     20
#define NB     4
#define Hh     480
#define Ww     640
#define hh     120
#define ww     160
#define FC     32
#define DC     32
#define NPIX   (hh*ww)           // 19200
#define NPIXH  (Hh*Ww)           // 307200
#define TOTPX  (Rn*NB*NPIX)      // 1,536,000
#define RB     (Rn*NB)           // 80
#define PADH   (hh+2)            // 122
#define PADW   (ww+2)            // 162
#define PADPIX (PADH*PADW)       // 19764
#define TOTPAD (RB*PADPIX)       // 1,581,120
#define MTILE  512
#define TILES1 39                // ceil(PADPIX/512)
#define STRIP1 838               // 512 + 2*163
#define SPITCH 80                // smem row pitch (bytes)
#define BIAS_I 1282
#define EPSF   1e-6f
#define BETAF  0.01f

// ---------------- device scratch ----------------
__device__ __nv_bfloat16 g_xTb[(size_t)NB*Hh*Ww*FC];      // [b][y][x][c] bf16
__device__ uint32_t     g_bfrag1[18*4*32*2];              // conv1 B fragments
__device__ uint32_t     g_bfrag2[18*32*2];                // conv2 B fragments
__device__ float        g_rg[TOTPX];
__device__ float        g_cx[TOTPX];
__device__ float        g_cy[TOTPX];
__device__ __nv_bfloat16 g_featp[(size_t)RB*PADPIX*32];   // padded, channel-last
__device__ __nv_bfloat16 g_attdp[(size_t)RB*PADPIX*32];   // padded, channel-last
__device__ float        g_num[Rn];
__device__ float        g_den[Rn];

// ---------------- helpers ----------------
__device__ __forceinline__ uint32_t smem_u32(const void* p) {
    uint32_t a;
    asm("{ .reg .u64 t; cvta.to.shared.u64 t, %1; cvt.u32.u64 %0, t; }"
        : "=r"(a) : "l"(p));
    return a;
}
__device__ __forceinline__ uint32_t pk2(float lo, float hi) {
    uint16_t l = __bfloat16_as_ushort(__float2bfloat16_rn(lo));
    uint16_t h = __bfloat16_as_ushort(__float2bfloat16_rn(hi));
    return (uint32_t)l | ((uint32_t)h << 16);
}
// accumulate 8 bf16 (uint4) * w into 4 float2
__device__ __forceinline__ void corner_acc(const uint4& v, float w, float2 acc[4]) {
    uint32_t u[4] = {v.x, v.y, v.z, v.w};
    #pragma unroll
    for (int i = 0; i < 4; i++) {
        float lo = __uint_as_float(u[i] << 16);
        float hi = __uint_as_float(u[i] & 0xffff0000u);
        acc[i].x = fmaf(w, lo, acc[i].x);
        acc[i].y = fmaf(w, hi, acc[i].y);
    }
}

// ---------------- x transpose: [b][c][y][x] -> [b][y][x][c] bf16 -----------
__global__ void k_transpose_x(const float* __restrict__ x) {
    __shared__ float tile[32][33];
    int b = blockIdx.z, y = blockIdx.y, x0 = blockIdx.x * 32;
    for (int c = threadIdx.y; c < 32; c += 8)
        tile[c][threadIdx.x] = x[(((size_t)b*32 + c)*Hh + y)*Ww + x0 + threadIdx.x];
    __syncthreads();
    for (int xx = threadIdx.y; xx < 32; xx += 8)
        g_xTb[(((size_t)b*Hh + y)*Ww + x0 + xx)*32 + threadIdx.x] =
            __float2bfloat16_rn(tile[threadIdx.x][xx]);
}

// ---------------- weight -> per-lane mma B fragments (+ zero accums) -------
__global__ void k_prep(const float* __restrict__ wa, const float* __restrict__ wp) {
    int e = blockIdx.x * 256 + threadIdx.x;
    if (e < 2304) {             // conv1: 18 kchunks x 4 ntiles x 32 lanes
        int lane = e & 31, nt = (e >> 5) & 3, kchunk = e >> 7;
        int tap = kchunk >> 1, kc = kchunk & 1;
        int ky = tap / 3, kx = tap % 3;
        int n  = nt * 8 + (lane >> 2);
        int ci = kc * 16 + (lane & 3) * 2;
        float w0 = wa[((n*32 + ci    )*3 + ky)*3 + kx];
        float w1 = wa[((n*32 + ci + 1)*3 + ky)*3 + kx];
        float w2 = wa[((n*32 + ci + 8)*3 + ky)*3 + kx];
        float w3 = wa[((n*32 + ci + 9)*3 + ky)*3 + kx];
        g_bfrag1[e*2 + 0] = pk2(w0, w1);
        g_bfrag1[e*2 + 1] = pk2(w2, w3);
    } else if (e < 2880) {      // conv2: 18 kchunks x 32 lanes
        int e2 = e - 2304;
        int lane = e2 & 31, kchunk = e2 >> 5;
        int tap = kchunk >> 1, kc = kchunk & 1;
        int ky = tap / 3, kx = tap % 3;
        int n  = lane >> 2;
        int ci = kc * 16 + (lane & 3) * 2;
        float w0 = 0.f, w1 = 0.f, w2 = 0.f, w3 = 0.f;
        if (n < 4) {
            w0 = wp[((n*32 + ci    )*3 + ky)*3 + kx];
            w1 = wp[((n*32 + ci + 1)*3 + ky)*3 + kx];
            w2 = wp[((n*32 + ci + 8)*3 + ky)*3 + kx];
            w3 = wp[((n*32 + ci + 9)*3 + ky)*3 + kx];
        }
        g_bfrag2[e2*2 + 0] = pk2(w0, w1);
        g_bfrag2[e2*2 + 1] = pk2(w2, w3);
    } else if (e < 2880 + Rn) {
        g_num[e - 2880] = 0.0f;
        g_den[e - 2880] = 0.0f;
    }
}

// ---------------- random pooling + coordinate maps ----------------
__global__ void k_pool(const float* __restrict__ gts, const float* __restrict__ rnd) {
    int tid = blockIdx.x * 256 + threadIdx.x;
    if (tid >= TOTPX) return;
    int ox = tid % ww; int t2 = tid / ww;
    int oy = t2 % hh;  t2 /= hh;
    int b  = t2 % NB;  int r = t2 / NB;
    const float* rp = rnd + (size_t)(r*NB + b) * NPIXH;
    const float* gp = gts + (size_t)b * NPIXH;
    int gy0 = oy * 4, gx0 = ox * 4;
    float best = -1.0f; int bi = 0, bj = 0;
    #pragma unroll
    for (int i = 0; i < 4; i++) {
        const float4 rv = *(const float4*)(rp + (size_t)(gy0 + i)*Ww + gx0);
        const float4 gv = *(const float4*)(gp + (size_t)(gy0 + i)*Ww + gx0);
        float rr[4] = {rv.x, rv.y, rv.z, rv.w};
        float gg[4] = {gv.x, gv.y, gv.z, gv.w};
        #pragma unroll
        for (int j = 0; j < 4; j++) {
            float m = (gg[j] > 0.1f) ? rr[j] : 0.0f;
            if (m > best) { best = m; bi = i; bj = j; }
        }
    }
    int row = gy0 + bi, col = gx0 + bj;
    float g = gp[(size_t)row*Ww + col];
    g_rg[tid] = (g < 0.1f) ? 0.0f : g;
    int idx = row * Ww + col + BIAS_I;
    int qy = idx / Ww; int qx = idx - qy * Ww;
    g_cx[tid] = ((float)qx / (float)Ww) * (float)(Ww - 1);
    g_cy[tid] = ((float)qy / (float)Hh) * (float)(Hh - 1);
}

// ---------------- bilinear gather: 4 lanes/pixel, uint4 corner loads -------
__global__ void __launch_bounds__(256) k_samplep() {
    int gid = blockIdx.x * 256 + threadIdx.x;
    int pix = gid >> 2;          // padded pixel index
    int q   = gid & 3;           // channel quad (8 channels = 16B)
    if (pix >= TOTPAD) return;
    int p  = pix % PADPIX;
    int rb = pix / PADPIX;
    int py = p / PADW, px = p - py * PADW;
    float2 acc[4] = {{0.f,0.f},{0.f,0.f},{0.f,0.f},{0.f,0.f}};
    if (py >= 1 && py <= hh && px >= 1 && px <= ww) {
        int tid = rb * NPIX + (py - 1) * ww + (px - 1);
        float cx = g_cx[tid], cy = g_cy[tid];
        float fx = floorf(cx), fy = floorf(cy);
        int x0 = (int)fx, y0 = (int)fy;
        float wx = cx - fx, wy = cy - fy;
        int b = rb & 3;
        // x0 and x0+1 always within [0, Ww-1] by construction of cx
        const uint4* base = (const uint4*)(g_xTb + (size_t)b * Hh * Ww * 32) + q;
        float w00 = (1.f - wx) * (1.f - wy), w10 = wx * (1.f - wy);
        float w01 = (1.f - wx) * wy,         w11 = wx * wy;
        if (y0 <= Hh - 1) {
            corner_acc(base[((size_t)y0*Ww + x0)*4],     w00, acc);
            corner_acc(base[((size_t)y0*Ww + x0 + 1)*4], w10, acc);
        }
        if (y0 + 1 <= Hh - 1) {
            corner_acc(base[((size_t)(y0+1)*Ww + x0)*4],     w01, acc);
            corner_acc(base[((size_t)(y0+1)*Ww + x0 + 1)*4], w11, acc);
        }
    }
    uint4 o;
    o.x = pk2(acc[0].x, acc[0].y);
    o.y = pk2(acc[1].x, acc[1].y);
    o.z = pk2(acc[2].x, acc[2].y);
    o.w = pk2(acc[3].x, acc[3].y);
    *((uint4*)(g_featp + (size_t)pix*32) + q) = o;
}

// ---------------- conv1: 9-tap bf16 MMA, M=512, + sigmoid*d -> attdp ------
// block: 256 thr (8 warps), each warp 64 flat pixels (4 m-subtiles of 16)
__global__ void __launch_bounds__(256, 2) k_conv1mma(const float* __restrict__ dten,
                                                     const float* __restrict__ batt) {
    extern __shared__ unsigned char smem[];
    unsigned char* s_strip = smem;                       // STRIP1*SPITCH = 67040
    uint32_t* s_bf = (uint32_t*)(smem + STRIP1*SPITCH);  // 4608 u32 = 18432
    int rb = blockIdx.y, tile = blockIdx.x;
    int p0 = tile * MTILE, base = p0 - 163;
    int t = threadIdx.x;
    const unsigned char* fp = (const unsigned char*)(g_featp + (size_t)rb * PADPIX * 32);

    for (int e = t; e < 4608; e += 256) s_bf[e] = g_bfrag1[e];
    for (int e = t; e < STRIP1*4; e += 256) {
        int r = e >> 2, j = e & 3;
        int gr = base + r;
        uint4 v = make_uint4(0,0,0,0);
        if (gr >= 0 && gr < PADPIX)
            v = *(const uint4*)(fp + (size_t)gr*64 + j*16);
        *(uint4*)(s_strip + r*SPITCH + j*16) = v;
    }
    __syncthreads();

    int warp = t >> 5, lane = t & 31;
    float acc[4][4][4] = {};
    uint32_t arow = smem_u32(s_strip) + (warp*64 + (lane & 15))*SPITCH + (lane >> 4)*16;

    #pragma unroll
    for (int tap = 0; tap < 9; tap++) {
        int tl = (tap/3)*PADW + (tap%3);
        #pragma unroll
        for (int kc = 0; kc < 2; kc++) {
            int kchunk = tap*2 + kc;
            uint32_t b0[4], b1[4];
            #pragma unroll
            for (int nt = 0; nt < 4; nt++) {
                b0[nt] = s_bf[kchunk*256 + nt*64 + lane*2];
                b1[nt] = s_bf[kchunk*256 + nt*64 + lane*2 + 1];
            }
            #pragma unroll
            for (int ms = 0; ms < 4; ms++) {
                uint32_t a0,a1,a2,a3;
                uint32_t addr = arow + (ms*16 + tl)*SPITCH + kc*32;
                asm volatile("ldmatrix.sync.aligned.m8n8.x4.shared.b16 {%0,%1,%2,%3}, [%4];"
                    : "=r"(a0),"=r"(a1),"=r"(a2),"=r"(a3) : "r"(addr));
                #pragma unroll
                for (int nt = 0; nt < 4; nt++) {
                    asm volatile("mma.sync.aligned.m16n8k16.row.col.f32.bf16.bf16.f32 "
                        "{%0,%1,%2,%3}, {%4,%5,%6,%7}, {%8,%9}, {%0,%1,%2,%3};"
                        : "+f"(acc[ms][nt][0]),"+f"(acc[ms][nt][1]),
                          "+f"(acc[ms][nt][2]),"+f"(acc[ms][nt][3])
                        : "r"(a0),"r"(a1),"r"(a2),"r"(a3),"r"(b0[nt]),"r"(b1[nt]));
                }
            }
        }
    }
    // epilogue: bias -> sigmoid -> * d -> attdp; borders get zeros
    int b = rb & 3;
    int colb = (lane & 3) * 2;
    #pragma unroll
    for (int ms = 0; ms < 4; ms++) {
        #pragma unroll
        for (int rr = 0; rr < 2; rr++) {
            int m = warp*64 + ms*16 + (lane >> 2) + rr*8;
            int p = p0 + m;
            if (p >= PADPIX) continue;
            int py = p / PADW, px = p - py*PADW;
            __nv_bfloat16* op = g_attdp + ((size_t)rb*PADPIX + p)*32;
            if (py >= 1 && py <= hh && px >= 1 && px <= ww) {
                int y = py - 1, x = px - 1;
                #pragma unroll
                for (int nt = 0; nt < 4; nt++) {
                    int co0 = nt*8 + colb;
                    float v0 = acc[ms][nt][rr*2]     + batt[co0];
                    float v1 = acc[ms][nt][rr*2 + 1] + batt[co0 + 1];
                    float at0 = 1.0f / (1.0f + __expf(-v0));
                    float at1 = 1.0f / (1.0f + __expf(-v1));
                    float d0 = dten[(((size_t)b*DC + co0    )*hh + y)*ww + x];
                    float d1 = dten[(((size_t)b*DC + co0 + 1)*hh + y)*ww + x];
                    *reinterpret_cast<uint32_t*>(op + co0) = pk2(at0*d0, at1*d1);
                }
            } else {
                #pragma unroll
                for (int nt = 0; nt < 4; nt++)
                    *reinterpret_cast<uint32_t*>(op + nt*8 + colb) = 0u;
            }
        }
    }
}

// ---------------- conv2: 9-tap bf16 MMA, M=512, N=8(4 real) + fused loss ---
__global__ void __launch_bounds__(256, 2) k_conv2loss(const float* __restrict__ bpost) {
    extern __shared__ unsigned char smem[];
    unsigned char* s_strip = smem;                       // STRIP1*SPITCH
    uint32_t* s_bf = (uint32_t*)(smem + STRIP1*SPITCH);  // 1152 u32
    int rb = blockIdx.y, tile = blockIdx.x;
    int p0 = tile * MTILE, base = p0 - 163;
    int t = threadIdx.x;
    const unsigned char* ap = (const unsigned char*)(g_attdp + (size_t)rb * PADPIX * 32);

    for (int e = t; e < 1152; e += 256) s_bf[e] = g_bfrag2[e];
    for (int e = t; e < STRIP1*4; e += 256) {
        int r = e >> 2, j = e & 3;
        int gr = base + r;
        uint4 v = make_uint4(0,0,0,0);
        if (gr >= 0 && gr < PADPIX)
            v = *(const uint4*)(ap + (size_t)gr*64 + j*16);
        *(uint4*)(s_strip + r*SPITCH + j*16) = v;
    }
    __syncthreads();

    int warp = t >> 5, lane = t & 31;
    float acc[4][4] = {};
    uint32_t arow = smem_u32(s_strip) + (warp*64 + (lane & 15))*SPITCH + (lane >> 4)*16;

    #pragma unroll
    for (int tap = 0; tap < 9; tap++) {
        int tl = (tap/3)*PADW + (tap%3);
        #pragma unroll
        for (int kc = 0; kc < 2; kc++) {
            int kchunk = tap*2 + kc;
            uint32_t b0 = s_bf[kchunk*64 + lane*2];
            uint32_t b1 = s_bf[kchunk*64 + lane*2 + 1];
            #pragma unroll
            for (int ms = 0; ms < 4; ms++) {
                uint32_t a0,a1,a2,a3;
                uint32_t addr = arow + (ms*16 + tl)*SPITCH + kc*32;
                asm volatile("ldmatrix.sync.aligned.m8n8.x4.shared.b16 {%0,%1,%2,%3}, [%4];"
                    : "=r"(a0),"=r"(a1),"=r"(a2),"=r"(a3) : "r"(addr));
                asm volatile("mma.sync.aligned.m16n8k16.row.col.f32.bf16.bf16.f32 "
                    "{%0,%1,%2,%3}, {%4,%5,%6,%7}, {%8,%9}, {%0,%1,%2,%3};"
                    : "+f"(acc[ms][0]),"+f"(acc[ms][1]),"+f"(acc[ms][2]),"+f"(acc[ms][3])
                    : "r"(a0),"r"(a1),"r"(a2),"r"(a3),"r"(b0),"r"(b1));
            }
        }
    }

    // fused loss epilogue: ds = acc + bias; smooth-L1 against log-grads of rg
    const int dyk[4] = {0, 1, 1, 1};
    const int dxk[4] = {1, 1, 0, -1};
    float num = 0.0f, den = 0.0f;
    int colb = (lane & 3) * 2;   // co pair; only colb<4 contributes
    const float* rgp = g_rg + (size_t)rb * NPIX;
    if (colb < 4) {
        float bb0 = bpost[colb], bb1 = bpost[colb + 1];
        #pragma unroll
        for (int ms = 0; ms < 4; ms++) {
            #pragma unroll
            for (int rr = 0; rr < 2; rr++) {
                int m = warp*64 + ms*16 + (lane >> 2) + rr*8;
                int p = p0 + m;
                if (p >= PADPIX) continue;
                int py = p / PADW, px = p - py*PADW;
                if (py < 1 || py > hh || px < 1 || px > ww) continue;
                int y = py - 1, x = px - 1;
                float c = rgp[y*ww + x];
                if (c <= 0.1f) continue;
                float logc = __logf(c + EPSF);
                float ds[2] = { acc[ms][rr*2] + bb0, acc[ms][rr*2 + 1] + bb1 };
                #pragma unroll
                for (int cc = 0; cc < 2; cc++) {
                    int k = colb + cc;
                    int yn = y + dyk[k], xn = x + dxk[k];
                    if (yn < hh && xn >= 0 && xn < ww) {
                        float nb = rgp[yn*ww + xn];
                        if (nb > 0.1f) {
                            float grad = logc - __logf(nb + EPSF);
                            float a = fabsf(ds[cc] - grad);
                            float s = (a < BETAF) ? (0.5f/BETAF)*a*a : a - 0.5f*BETAF;
                            num += s; den += 1.0f;
                        }
                    }
                }
            }
        }
    }
    #pragma unroll
    for (int o = 16; o > 0; o >>= 1) {
        num += __shfl_down_sync(0xffffffffu, num, o);
        den += __shfl_down_sync(0xffffffffu, den, o);
    }
    if (lane == 0 && (num != 0.0f || den != 0.0f)) {
        int r = rb >> 2;
        atomicAdd(&g_num[r], num);
        atomicAdd(&g_den[r], den);
    }
}

// ---------------- final: mean of per-r ratios ----------------
__global__ void k_final(float* __restrict__ out) {
    int t = threadIdx.x;
    float v = (t < Rn) ? (g_num[t] / g_den[t]) : 0.0f;
    #pragma unroll
    for (int o = 16; o > 0; o >>= 1) v += __shfl_down_sync(0xffffffffu, v, o);
    if (t == 0) out[0] = v / (float)Rn;
}

// ---------------- launch ----------------
extern "C" void kernel_launch(void* const* d_in, const int* in_sizes, int n_in,
                              void* d_out, int out_size) {
    const float* x     = (const float*)d_in[0];
    const float* dten  = (const float*)d_in[1];
    const float* gts   = (const float*)d_in[2];
    const float* rnd   = (const float*)d_in[3];
    const float* Watt  = (const float*)d_in[4];
    const float* batt  = (const float*)d_in[5];
    const float* Wpost = (const float*)d_in[6];
    const float* bpost = (const float*)d_in[7];
    float* out = (float*)d_out;

    static int attr_done = 0;
    if (!attr_done) {
        cudaFuncSetAttribute(k_conv1mma, cudaFuncAttributeMaxDynamicSharedMemorySize,
                             STRIP1*SPITCH + 4608*4);
        cudaFuncSetAttribute(k_conv2loss, cudaFuncAttributeMaxDynamicSharedMemorySize,
                             STRIP1*SPITCH + 1152*4);
        attr_done = 1;
    }

    k_transpose_x<<<dim3(Ww/32, Hh, NB), dim3(32, 8)>>>(x);
    k_prep<<<12, 256>>>(Watt, Wpost);
    k_pool<<<TOTPX/256, 256>>>(gts, rnd);
    {
        long long tp = (long long)TOTPAD * 4;
        k_samplep<<<(unsigned)((tp + 255)/256), 256>>>();
    }
    k_conv1mma<<<dim3(TILES1, RB), 256, STRIP1*SPITCH + 4608*4>>>(dten, batt);
    k_conv2loss<<<dim3(TILES1, RB), 256, STRIP1*SPITCH + 1152*4>>>(bpost);
    k_final<<<1, 32>>>(out);
}

// round 6
// speedup vs baseline: 2.6815x; 1.1304x over previous
#include <cuda_runtime.h>
#include <cuda_bf16.h>
#include <cstdint>

// ---------------- problem constants ----------------
#define Rn     20
#define NB     4
#define Hh     480
#define Ww     640
#define hh     120
#define ww     160
#define FC     32
#define DC     32
#define NPIX   (hh*ww)           // 19200
#define NPIXH  (Hh*Ww)           // 307200
#define TOTPX  (Rn*NB*NPIX)      // 1,536,000
#define RB     (Rn*NB)           // 80
#define PADH   (hh+2)            // 122
#define PADW   (ww+2)            // 162
#define PADPIX (PADH*PADW)       // 19764
#define TOTPAD (RB*PADPIX)       // 1,581,120
#define MTILE  512
#define TILES1 39                // ceil(PADPIX/512)
#define STRIP1 838               // 512 + 2*163
#define SPITCH 80                // smem row pitch (bytes)
#define BIAS_I 1282
#define EPSF   1e-6f
#define BETAF  0.01f
#define TPBLKS 38400             // transpose blocks (20*480*4)

// ---------------- device scratch ----------------
__device__ __nv_bfloat16 g_xTb[(size_t)NB*Hh*Ww*FC];      // [b][y][x][c] bf16
__device__ uint32_t     g_bfrag1[18*4*32*2];              // conv1 B fragments
__device__ uint32_t     g_bfrag2[18*32*2];                // conv2 B fragments
__device__ float        g_rg[TOTPX];
__device__ float        g_cx[TOTPX];
__device__ float        g_cy[TOTPX];
__device__ __nv_bfloat16 g_featp[(size_t)RB*PADPIX*32];   // padded, channel-last
__device__ __nv_bfloat16 g_attdp[(size_t)RB*PADPIX*32];   // padded, channel-last
__device__ float        g_num[Rn];
__device__ float        g_den[Rn];

// ---------------- helpers ----------------
__device__ __forceinline__ uint32_t smem_u32(const void* p) {
    uint32_t a;
    asm("{ .reg .u64 t; cvta.to.shared.u64 t, %1; cvt.u32.u64 %0, t; }"
        : "=r"(a) : "l"(p));
    return a;
}
__device__ __forceinline__ uint32_t pk2(float lo, float hi) {
    uint16_t l = __bfloat16_as_ushort(__float2bfloat16_rn(lo));
    uint16_t h = __bfloat16_as_ushort(__float2bfloat16_rn(hi));
    return (uint32_t)l | ((uint32_t)h << 16);
}
// accumulate 8 bf16 (uint4) * w into 4 float2
__device__ __forceinline__ void corner_acc(const uint4& v, float w, float2 acc[4]) {
    uint32_t u[4] = {v.x, v.y, v.z, v.w};
    #pragma unroll
    for (int i = 0; i < 4; i++) {
        float lo = __uint_as_float(u[i] << 16);
        float hi = __uint_as_float(u[i] & 0xffff0000u);
        acc[i].x = fmaf(w, lo, acc[i].x);
        acc[i].y = fmaf(w, hi, acc[i].y);
    }
}
// 16B cp.async with zero-fill when invalid
__device__ __forceinline__ void cpa16(uint32_t dst, const void* src, bool valid) {
    int sz = valid ? 16 : 0;
    asm volatile("cp.async.cg.shared.global [%0], [%1], 16, %2;"
                 :: "r"(dst), "l"(src), "r"(sz));
}

// ---------------- fused: x transpose + weight fragments + zero accums ------
__global__ void __launch_bounds__(256) k_tp_prep(const float* __restrict__ x,
                                                 const float* __restrict__ wa,
                                                 const float* __restrict__ wp) {
    if (blockIdx.x < TPBLKS) {
        // transpose: [b][c][y][x] -> [b][y][x][c] bf16
        __shared__ float tile[32][33];
        int bid = blockIdx.x;
        int xb = bid % 20; int y = (bid / 20) % Hh; int b = bid / (20 * Hh);
        int x0 = xb * 32;
        int tx = threadIdx.x & 31, ty = threadIdx.x >> 5;
        for (int c = ty; c < 32; c += 8)
            tile[c][tx] = x[(((size_t)b*32 + c)*Hh + y)*Ww + x0 + tx];
        __syncthreads();
        for (int xx = ty; xx < 32; xx += 8)
            g_xTb[(((size_t)b*Hh + y)*Ww + x0 + xx)*32 + tx] =
                __float2bfloat16_rn(tile[tx][xx]);
        return;
    }
    int e = (blockIdx.x - TPBLKS) * 256 + threadIdx.x;
    if (e < 2304) {             // conv1: 18 kchunks x 4 ntiles x 32 lanes
        int lane = e & 31, nt = (e >> 5) & 3, kchunk = e >> 7;
        int tap = kchunk >> 1, kc = kchunk & 1;
        int ky = tap / 3, kx = tap % 3;
        int n  = nt * 8 + (lane >> 2);
        int ci = kc * 16 + (lane & 3) * 2;
        float w0 = wa[((n*32 + ci    )*3 + ky)*3 + kx];
        float w1 = wa[((n*32 + ci + 1)*3 + ky)*3 + kx];
        float w2 = wa[((n*32 + ci + 8)*3 + ky)*3 + kx];
        float w3 = wa[((n*32 + ci + 9)*3 + ky)*3 + kx];
        g_bfrag1[e*2 + 0] = pk2(w0, w1);
        g_bfrag1[e*2 + 1] = pk2(w2, w3);
    } else if (e < 2880) {      // conv2: 18 kchunks x 32 lanes
        int e2 = e - 2304;
        int lane = e2 & 31, kchunk = e2 >> 5;
        int tap = kchunk >> 1, kc = kchunk & 1;
        int ky = tap / 3, kx = tap % 3;
        int n  = lane >> 2;
        int ci = kc * 16 + (lane & 3) * 2;
        float w0 = 0.f, w1 = 0.f, w2 = 0.f, w3 = 0.f;
        if (n < 4) {
            w0 = wp[((n*32 + ci    )*3 + ky)*3 + kx];
            w1 = wp[((n*32 + ci + 1)*3 + ky)*3 + kx];
            w2 = wp[((n*32 + ci + 8)*3 + ky)*3 + kx];
            w3 = wp[((n*32 + ci + 9)*3 + ky)*3 + kx];
        }
        g_bfrag2[e2*2 + 0] = pk2(w0, w1);
        g_bfrag2[e2*2 + 1] = pk2(w2, w3);
    } else if (e < 2880 + Rn) {
        g_num[e - 2880] = 0.0f;
        g_den[e - 2880] = 0.0f;
    }
}

// ---------------- random pooling + coordinate maps ----------------
__global__ void k_pool(const float* __restrict__ gts, const float* __restrict__ rnd) {
    int tid = blockIdx.x * 256 + threadIdx.x;
    if (tid >= TOTPX) return;
    int ox = tid % ww; int t2 = tid / ww;
    int oy = t2 % hh;  t2 /= hh;
    int b  = t2 % NB;  int r = t2 / NB;
    const float* rp = rnd + (size_t)(r*NB + b) * NPIXH;
    const float* gp = gts + (size_t)b * NPIXH;
    int gy0 = oy * 4, gx0 = ox * 4;
    float best = -1.0f; int bi = 0, bj = 0;
    #pragma unroll
    for (int i = 0; i < 4; i++) {
        const float4 rv = *(const float4*)(rp + (size_t)(gy0 + i)*Ww + gx0);
        const float4 gv = *(const float4*)(gp + (size_t)(gy0 + i)*Ww + gx0);
        float rr[4] = {rv.x, rv.y, rv.z, rv.w};
        float gg[4] = {gv.x, gv.y, gv.z, gv.w};
        #pragma unroll
        for (int j = 0; j < 4; j++) {
            float m = (gg[j] > 0.1f) ? rr[j] : 0.0f;
            if (m > best) { best = m; bi = i; bj = j; }
        }
    }
    int row = gy0 + bi, col = gx0 + bj;
    float g = gp[(size_t)row*Ww + col];
    g_rg[tid] = (g < 0.1f) ? 0.0f : g;
    int idx = row * Ww + col + BIAS_I;
    int qy = idx / Ww; int qx = idx - qy * Ww;
    g_cx[tid] = ((float)qx / (float)Ww) * (float)(Ww - 1);
    g_cy[tid] = ((float)qy / (float)Hh) * (float)(Hh - 1);
}

// ---------------- bilinear gather: 4 lanes/pixel, uint4 corner loads -------
__global__ void __launch_bounds__(256) k_samplep() {
    int gid = blockIdx.x * 256 + threadIdx.x;
    int pix = gid >> 2;          // padded pixel index
    int q   = gid & 3;           // channel quad (8 channels = 16B)
    if (pix >= TOTPAD) return;
    int p  = pix % PADPIX;
    int rb = pix / PADPIX;
    int py = p / PADW, px = p - py * PADW;
    float2 acc[4] = {{0.f,0.f},{0.f,0.f},{0.f,0.f},{0.f,0.f}};
    if (py >= 1 && py <= hh && px >= 1 && px <= ww) {
        int tid = rb * NPIX + (py - 1) * ww + (px - 1);
        float cx = g_cx[tid], cy = g_cy[tid];
        float fx = floorf(cx), fy = floorf(cy);
        int x0 = (int)fx, y0 = (int)fy;
        float wx = cx - fx, wy = cy - fy;
        int b = rb & 3;
        const uint4* base = (const uint4*)(g_xTb + (size_t)b * Hh * Ww * 32) + q;
        float w00 = (1.f - wx) * (1.f - wy), w10 = wx * (1.f - wy);
        float w01 = (1.f - wx) * wy,         w11 = wx * wy;
        if (y0 <= Hh - 1) {
            corner_acc(base[((size_t)y0*Ww + x0)*4],     w00, acc);
            corner_acc(base[((size_t)y0*Ww + x0 + 1)*4], w10, acc);
        }
        if (y0 + 1 <= Hh - 1) {
            corner_acc(base[((size_t)(y0+1)*Ww + x0)*4],     w01, acc);
            corner_acc(base[((size_t)(y0+1)*Ww + x0 + 1)*4], w11, acc);
        }
    }
    uint4 o;
    o.x = pk2(acc[0].x, acc[0].y);
    o.y = pk2(acc[1].x, acc[1].y);
    o.z = pk2(acc[2].x, acc[2].y);
    o.w = pk2(acc[3].x, acc[3].y);
    *((uint4*)(g_featp + (size_t)pix*32) + q) = o;
}

// ---------------- conv1: 9-tap bf16 MMA, M=512, + sigmoid*d -> attdp ------
// block: 256 thr (8 warps), each warp 64 flat pixels (4 m-subtiles of 16)
__global__ void __launch_bounds__(256, 2) k_conv1mma(const float* __restrict__ dten,
                                                     const float* __restrict__ batt) {
    extern __shared__ unsigned char smem[];
    unsigned char* s_strip = smem;                       // STRIP1*SPITCH = 67040
    uint32_t* s_bf = (uint32_t*)(smem + STRIP1*SPITCH);  // 4608 u32 = 18432
    int rb = blockIdx.y, tile = blockIdx.x;
    int p0 = tile * MTILE, base = p0 - 163;
    int t = threadIdx.x;
    const unsigned char* fp = (const unsigned char*)(g_featp + (size_t)rb * PADPIX * 32);

    // async strip fill (zero-fill OOB), overlapped with weight-frag loads
    uint32_t sbase = smem_u32(s_strip);
    for (int e = t; e < STRIP1*4; e += 256) {
        int r = e >> 2, j = e & 3;
        int gr = base + r;
        bool v = (gr >= 0 && gr < PADPIX);
        cpa16(sbase + r*SPITCH + j*16, fp + (size_t)(v ? gr : 0)*64 + j*16, v);
    }
    asm volatile("cp.async.commit_group;" ::: "memory");
    for (int e = t; e < 4608; e += 256) s_bf[e] = g_bfrag1[e];
    asm volatile("cp.async.wait_group 0;" ::: "memory");
    __syncthreads();

    int warp = t >> 5, lane = t & 31;
    float acc[4][4][4] = {};
    uint32_t arow = sbase + (warp*64 + (lane & 15))*SPITCH + (lane >> 4)*16;

    #pragma unroll
    for (int tap = 0; tap < 9; tap++) {
        int tl = (tap/3)*PADW + (tap%3);
        #pragma unroll
        for (int kc = 0; kc < 2; kc++) {
            int kchunk = tap*2 + kc;
            uint32_t b0[4], b1[4];
            #pragma unroll
            for (int nt = 0; nt < 4; nt++) {
                b0[nt] = s_bf[kchunk*256 + nt*64 + lane*2];
                b1[nt] = s_bf[kchunk*256 + nt*64 + lane*2 + 1];
            }
            #pragma unroll
            for (int ms = 0; ms < 4; ms++) {
                uint32_t a0,a1,a2,a3;
                uint32_t addr = arow + (ms*16 + tl)*SPITCH + kc*32;
                asm volatile("ldmatrix.sync.aligned.m8n8.x4.shared.b16 {%0,%1,%2,%3}, [%4];"
                    : "=r"(a0),"=r"(a1),"=r"(a2),"=r"(a3) : "r"(addr));
                #pragma unroll
                for (int nt = 0; nt < 4; nt++) {
                    asm volatile("mma.sync.aligned.m16n8k16.row.col.f32.bf16.bf16.f32 "
                        "{%0,%1,%2,%3}, {%4,%5,%6,%7}, {%8,%9}, {%0,%1,%2,%3};"
                        : "+f"(acc[ms][nt][0]),"+f"(acc[ms][nt][1]),
                          "+f"(acc[ms][nt][2]),"+f"(acc[ms][nt][3])
                        : "r"(a0),"r"(a1),"r"(a2),"r"(a3),"r"(b0[nt]),"r"(b1[nt]));
                }
            }
        }
    }
    // epilogue: bias -> sigmoid -> * d -> attdp; borders get zeros
    int b = rb & 3;
    int colb = (lane & 3) * 2;
    #pragma unroll
    for (int ms = 0; ms < 4; ms++) {
        #pragma unroll
        for (int rr = 0; rr < 2; rr++) {
            int m = warp*64 + ms*16 + (lane >> 2) + rr*8;
            int p = p0 + m;
            if (p >= PADPIX) continue;
            int py = p / PADW, px = p - py*PADW;
            __nv_bfloat16* op = g_attdp + ((size_t)rb*PADPIX + p)*32;
            if (py >= 1 && py <= hh && px >= 1 && px <= ww) {
                int y = py - 1, x = px - 1;
                #pragma unroll
                for (int nt = 0; nt < 4; nt++) {
                    int co0 = nt*8 + colb;
                    float v0 = acc[ms][nt][rr*2]     + batt[co0];
                    float v1 = acc[ms][nt][rr*2 + 1] + batt[co0 + 1];
                    float at0 = 1.0f / (1.0f + __expf(-v0));
                    float at1 = 1.0f / (1.0f + __expf(-v1));
                    float d0 = dten[(((size_t)b*DC + co0    )*hh + y)*ww + x];
                    float d1 = dten[(((size_t)b*DC + co0 + 1)*hh + y)*ww + x];
                    *reinterpret_cast<uint32_t*>(op + co0) = pk2(at0*d0, at1*d1);
                }
            } else {
                #pragma unroll
                for (int nt = 0; nt < 4; nt++)
                    *reinterpret_cast<uint32_t*>(op + nt*8 + colb) = 0u;
            }
        }
    }
}

// ---------------- conv2: 9-tap bf16 MMA, M=512, N=8(4 real) + fused loss ---
__global__ void __launch_bounds__(256, 2) k_conv2loss(const float* __restrict__ bpost) {
    extern __shared__ unsigned char smem[];
    unsigned char* s_strip = smem;                       // STRIP1*SPITCH
    uint32_t* s_bf = (uint32_t*)(smem + STRIP1*SPITCH);  // 1152 u32
    int rb = blockIdx.y, tile = blockIdx.x;
    int p0 = tile * MTILE, base = p0 - 163;
    int t = threadIdx.x;
    const unsigned char* ap = (const unsigned char*)(g_attdp + (size_t)rb * PADPIX * 32);

    uint32_t sbase = smem_u32(s_strip);
    for (int e = t; e < STRIP1*4; e += 256) {
        int r = e >> 2, j = e & 3;
        int gr = base + r;
        bool v = (gr >= 0 && gr < PADPIX);
        cpa16(sbase + r*SPITCH + j*16, ap + (size_t)(v ? gr : 0)*64 + j*16, v);
    }
    asm volatile("cp.async.commit_group;" ::: "memory");
    for (int e = t; e < 1152; e += 256) s_bf[e] = g_bfrag2[e];
    asm volatile("cp.async.wait_group 0;" ::: "memory");
    __syncthreads();

    int warp = t >> 5, lane = t & 31;
    float acc[4][4] = {};
    uint32_t arow = sbase + (warp*64 + (lane & 15))*SPITCH + (lane >> 4)*16;

    #pragma unroll
    for (int tap = 0; tap < 9; tap++) {
        int tl = (tap/3)*PADW + (tap%3);
        #pragma unroll
        for (int kc = 0; kc < 2; kc++) {
            int kchunk = tap*2 + kc;
            uint32_t b0 = s_bf[kchunk*64 + lane*2];
            uint32_t b1 = s_bf[kchunk*64 + lane*2 + 1];
            #pragma unroll
            for (int ms = 0; ms < 4; ms++) {
                uint32_t a0,a1,a2,a3;
                uint32_t addr = arow + (ms*16 + tl)*SPITCH + kc*32;
                asm volatile("ldmatrix.sync.aligned.m8n8.x4.shared.b16 {%0,%1,%2,%3}, [%4];"
                    : "=r"(a0),"=r"(a1),"=r"(a2),"=r"(a3) : "r"(addr));
                asm volatile("mma.sync.aligned.m16n8k16.row.col.f32.bf16.bf16.f32 "
                    "{%0,%1,%2,%3}, {%4,%5,%6,%7}, {%8,%9}, {%0,%1,%2,%3};"
                    : "+f"(acc[ms][0]),"+f"(acc[ms][1]),"+f"(acc[ms][2]),"+f"(acc[ms][3])
                    : "r"(a0),"r"(a1),"r"(a2),"r"(a3),"r"(b0),"r"(b1));
            }
        }
    }

    // fused loss epilogue: ds = acc + bias; smooth-L1 against log-grads of rg
    const int dyk[4] = {0, 1, 1, 1};
    const int dxk[4] = {1, 1, 0, -1};
    float num = 0.0f, den = 0.0f;
    int colb = (lane & 3) * 2;   // co pair; only colb<4 contributes
    const float* rgp = g_rg + (size_t)rb * NPIX;
    if (colb < 4) {
        float bb0 = bpost[colb], bb1 = bpost[colb + 1];
        #pragma unroll
        for (int ms = 0; ms < 4; ms++) {
            #pragma unroll
            for (int rr = 0; rr < 2; rr++) {
                int m = warp*64 + ms*16 + (lane >> 2) + rr*8;
                int p = p0 + m;
                if (p >= PADPIX) continue;
                int py = p / PADW, px = p - py*PADW;
                if (py < 1 || py > hh || px < 1 || px > ww) continue;
                int y = py - 1, x = px - 1;
                float c = rgp[y*ww + x];
                if (c <= 0.1f) continue;
                float logc = __logf(c + EPSF);
                float ds[2] = { acc[ms][rr*2] + bb0, acc[ms][rr*2 + 1] + bb1 };
                #pragma unroll
                for (int cc = 0; cc < 2; cc++) {
                    int k = colb + cc;
                    int yn = y + dyk[k], xn = x + dxk[k];
                    if (yn < hh && xn >= 0 && xn < ww) {
                        float nb = rgp[yn*ww + xn];
                        if (nb > 0.1f) {
                            float grad = logc - __logf(nb + EPSF);
                            float a = fabsf(ds[cc] - grad);
                            float s = (a < BETAF) ? (0.5f/BETAF)*a*a : a - 0.5f*BETAF;
                            num += s; den += 1.0f;
                        }
                    }
                }
            }
        }
    }
    #pragma unroll
    for (int o = 16; o > 0; o >>= 1) {
        num += __shfl_down_sync(0xffffffffu, num, o);
        den += __shfl_down_sync(0xffffffffu, den, o);
    }
    if (lane == 0 && (num != 0.0f || den != 0.0f)) {
        int r = rb >> 2;
        atomicAdd(&g_num[r], num);
        atomicAdd(&g_den[r], den);
    }
}

// ---------------- final: mean of per-r ratios ----------------
__global__ void k_final(float* __restrict__ out) {
    int t = threadIdx.x;
    float v = (t < Rn) ? (g_num[t] / g_den[t]) : 0.0f;
    #pragma unroll
    for (int o = 16; o > 0; o >>= 1) v += __shfl_down_sync(0xffffffffu, v, o);
    if (t == 0) out[0] = v / (float)Rn;
}

// ---------------- launch ----------------
extern "C" void kernel_launch(void* const* d_in, const int* in_sizes, int n_in,
                              void* d_out, int out_size) {
    const float* x     = (const float*)d_in[0];
    const float* dten  = (const float*)d_in[1];
    const float* gts   = (const float*)d_in[2];
    const float* rnd   = (const float*)d_in[3];
    const float* Watt  = (const float*)d_in[4];
    const float* batt  = (const float*)d_in[5];
    const float* Wpost = (const float*)d_in[6];
    const float* bpost = (const float*)d_in[7];
    float* out = (float*)d_out;

    static int attr_done = 0;
    if (!attr_done) {
        cudaFuncSetAttribute(k_conv1mma, cudaFuncAttributeMaxDynamicSharedMemorySize,
                             STRIP1*SPITCH + 4608*4);
        cudaFuncSetAttribute(k_conv2loss, cudaFuncAttributeMaxDynamicSharedMemorySize,
                             STRIP1*SPITCH + 1152*4);
        attr_done = 1;
    }

    k_tp_prep<<<TPBLKS + 12, 256>>>(x, Watt, Wpost);
    k_pool<<<TOTPX/256, 256>>>(gts, rnd);
    {
        long long tp = (long long)TOTPAD * 4;
        k_samplep<<<(unsigned)((tp + 255)/256), 256>>>();
    }
    k_conv1mma<<<dim3(TILES1, RB), 256, STRIP1*SPITCH + 4608*4>>>(dten, batt);
    k_conv2loss<<<dim3(TILES1, RB), 256, STRIP1*SPITCH + 1152*4>>>(bpost);
    k_final<<<1, 32>>>(out);
}

// round 7
// speedup vs baseline: 2.7979x; 1.0434x over previous
#include <cuda_runtime.h>
#include <cuda_bf16.h>
#include <cstdint>

// ---------------- problem constants ----------------
#define Rn     20
#define NB     4
#define Hh     480
#define Ww     640
#define hh     120
#define ww     160
#define FC     32
#define DC     32
#define NPIX   (hh*ww)           // 19200
#define NPIXH  (Hh*Ww)           // 307200
#define TOTPX  (Rn*NB*NPIX)      // 1,536,000
#define RB     (Rn*NB)           // 80
#define PADH   (hh+2)            // 122
#define PADW   (ww+2)            // 162
#define PADPIX (PADH*PADW)       // 19764
#define TOTPAD (RB*PADPIX)       // 1,581,120
#define MTILE  256
#define TILES1 78                // ceil(PADPIX/256)
#define STRIP1 582               // 256 + 2*163
#define SPITCH 80                // smem row pitch (bytes)
#define BIAS_I 1282
#define EPSF   1e-6f
#define BETAF  0.01f
#define TPBLKS 38400             // transpose blocks (20*480*4)

// ---------------- device scratch ----------------
__device__ __nv_bfloat16 g_xTb[(size_t)NB*Hh*Ww*FC];      // [b][y][x][c] bf16
__device__ uint32_t     g_bfrag1[18*4*32*2];              // conv1 B fragments
__device__ uint32_t     g_bfrag2[18*32*2];                // conv2 B fragments
__device__ float        g_rg[TOTPX];
__device__ float        g_cx[TOTPX];
__device__ float        g_cy[TOTPX];
__device__ __nv_bfloat16 g_featp[(size_t)RB*PADPIX*32];   // padded, channel-last
__device__ __nv_bfloat16 g_attdp[(size_t)RB*PADPIX*32];   // padded, channel-last
__device__ float        g_num[Rn];
__device__ float        g_den[Rn];

// ---------------- helpers ----------------
__device__ __forceinline__ uint32_t smem_u32(const void* p) {
    uint32_t a;
    asm("{ .reg .u64 t; cvta.to.shared.u64 t, %1; cvt.u32.u64 %0, t; }"
        : "=r"(a) : "l"(p));
    return a;
}
__device__ __forceinline__ uint32_t pk2(float lo, float hi) {
    uint16_t l = __bfloat16_as_ushort(__float2bfloat16_rn(lo));
    uint16_t h = __bfloat16_as_ushort(__float2bfloat16_rn(hi));
    return (uint32_t)l | ((uint32_t)h << 16);
}
// accumulate 8 bf16 (uint4) * w into 4 float2
__device__ __forceinline__ void corner_acc(const uint4& v, float w, float2 acc[4]) {
    uint32_t u[4] = {v.x, v.y, v.z, v.w};
    #pragma unroll
    for (int i = 0; i < 4; i++) {
        float lo = __uint_as_float(u[i] << 16);
        float hi = __uint_as_float(u[i] & 0xffff0000u);
        acc[i].x = fmaf(w, lo, acc[i].x);
        acc[i].y = fmaf(w, hi, acc[i].y);
    }
}
// 16B cp.async with zero-fill when invalid
__device__ __forceinline__ void cpa16(uint32_t dst, const void* src, bool valid) {
    int sz = valid ? 16 : 0;
    asm volatile("cp.async.cg.shared.global [%0], [%1], 16, %2;"
                 :: "r"(dst), "l"(src), "r"(sz));
}

// ---------------- fused: x transpose + weight fragments + zero accums ------
__global__ void __launch_bounds__(256) k_tp_prep(const float* __restrict__ x,
                                                 const float* __restrict__ wa,
                                                 const float* __restrict__ wp) {
    if (blockIdx.x < TPBLKS) {
        __shared__ float tile[32][33];
        int bid = blockIdx.x;
        int xb = bid % 20; int y = (bid / 20) % Hh; int b = bid / (20 * Hh);
        int x0 = xb * 32;
        int tx = threadIdx.x & 31, ty = threadIdx.x >> 5;
        for (int c = ty; c < 32; c += 8)
            tile[c][tx] = x[(((size_t)b*32 + c)*Hh + y)*Ww + x0 + tx];
        __syncthreads();
        for (int xx = ty; xx < 32; xx += 8)
            g_xTb[(((size_t)b*Hh + y)*Ww + x0 + xx)*32 + tx] =
                __float2bfloat16_rn(tile[tx][xx]);
        return;
    }
    int e = (blockIdx.x - TPBLKS) * 256 + threadIdx.x;
    if (e < 2304) {             // conv1: 18 kchunks x 4 ntiles x 32 lanes
        int lane = e & 31, nt = (e >> 5) & 3, kchunk = e >> 7;
        int tap = kchunk >> 1, kc = kchunk & 1;
        int ky = tap / 3, kx = tap % 3;
        int n  = nt * 8 + (lane >> 2);
        int ci = kc * 16 + (lane & 3) * 2;
        float w0 = wa[((n*32 + ci    )*3 + ky)*3 + kx];
        float w1 = wa[((n*32 + ci + 1)*3 + ky)*3 + kx];
        float w2 = wa[((n*32 + ci + 8)*3 + ky)*3 + kx];
        float w3 = wa[((n*32 + ci + 9)*3 + ky)*3 + kx];
        g_bfrag1[e*2 + 0] = pk2(w0, w1);
        g_bfrag1[e*2 + 1] = pk2(w2, w3);
    } else if (e < 2880) {      // conv2: 18 kchunks x 32 lanes
        int e2 = e - 2304;
        int lane = e2 & 31, kchunk = e2 >> 5;
        int tap = kchunk >> 1, kc = kchunk & 1;
        int ky = tap / 3, kx = tap % 3;
        int n  = lane >> 2;
        int ci = kc * 16 + (lane & 3) * 2;
        float w0 = 0.f, w1 = 0.f, w2 = 0.f, w3 = 0.f;
        if (n < 4) {
            w0 = wp[((n*32 + ci    )*3 + ky)*3 + kx];
            w1 = wp[((n*32 + ci + 1)*3 + ky)*3 + kx];
            w2 = wp[((n*32 + ci + 8)*3 + ky)*3 + kx];
            w3 = wp[((n*32 + ci + 9)*3 + ky)*3 + kx];
        }
        g_bfrag2[e2*2 + 0] = pk2(w0, w1);
        g_bfrag2[e2*2 + 1] = pk2(w2, w3);
    } else if (e < 2880 + Rn) {
        g_num[e - 2880] = 0.0f;
        g_den[e - 2880] = 0.0f;
    }
}

// ---------------- random pooling + coordinate maps ----------------
__global__ void k_pool(const float* __restrict__ gts, const float* __restrict__ rnd) {
    int tid = blockIdx.x * 256 + threadIdx.x;
    if (tid >= TOTPX) return;
    int ox = tid % ww; int t2 = tid / ww;
    int oy = t2 % hh;  t2 /= hh;
    int b  = t2 % NB;  int r = t2 / NB;
    const float* rp = rnd + (size_t)(r*NB + b) * NPIXH;
    const float* gp = gts + (size_t)b * NPIXH;
    int gy0 = oy * 4, gx0 = ox * 4;
    float best = -1.0f; int bi = 0, bj = 0;
    #pragma unroll
    for (int i = 0; i < 4; i++) {
        const float4 rv = *(const float4*)(rp + (size_t)(gy0 + i)*Ww + gx0);
        const float4 gv = *(const float4*)(gp + (size_t)(gy0 + i)*Ww + gx0);
        float rr[4] = {rv.x, rv.y, rv.z, rv.w};
        float gg[4] = {gv.x, gv.y, gv.z, gv.w};
        #pragma unroll
        for (int j = 0; j < 4; j++) {
            float m = (gg[j] > 0.1f) ? rr[j] : 0.0f;
            if (m > best) { best = m; bi = i; bj = j; }
        }
    }
    int row = gy0 + bi, col = gx0 + bj;
    float g = gp[(size_t)row*Ww + col];
    g_rg[tid] = (g < 0.1f) ? 0.0f : g;
    int idx = row * Ww + col + BIAS_I;
    int qy = idx / Ww; int qx = idx - qy * Ww;
    g_cx[tid] = ((float)qx / (float)Ww) * (float)(Ww - 1);
    g_cy[tid] = ((float)qy / (float)Hh) * (float)(Hh - 1);
}

// ---------------- bilinear gather: 4 lanes/pixel, uint4 corner loads -------
__global__ void __launch_bounds__(256) k_samplep() {
    int gid = blockIdx.x * 256 + threadIdx.x;
    int pix = gid >> 2;          // padded pixel index
    int q   = gid & 3;           // channel quad (8 channels = 16B)
    if (pix >= TOTPAD) return;
    int p  = pix % PADPIX;
    int rb = pix / PADPIX;
    int py = p / PADW, px = p - py * PADW;
    float2 acc[4] = {{0.f,0.f},{0.f,0.f},{0.f,0.f},{0.f,0.f}};
    if (py >= 1 && py <= hh && px >= 1 && px <= ww) {
        int tid = rb * NPIX + (py - 1) * ww + (px - 1);
        float cx = g_cx[tid], cy = g_cy[tid];
        float fx = floorf(cx), fy = floorf(cy);
        int x0 = (int)fx, y0 = (int)fy;
        float wx = cx - fx, wy = cy - fy;
        int b = rb & 3;
        const uint4* base = (const uint4*)(g_xTb + (size_t)b * Hh * Ww * 32) + q;
        float w00 = (1.f - wx) * (1.f - wy), w10 = wx * (1.f - wy);
        float w01 = (1.f - wx) * wy,         w11 = wx * wy;
        if (y0 <= Hh - 1) {
            corner_acc(base[((size_t)y0*Ww + x0)*4],     w00, acc);
            corner_acc(base[((size_t)y0*Ww + x0 + 1)*4], w10, acc);
        }
        if (y0 + 1 <= Hh - 1) {
            corner_acc(base[((size_t)(y0+1)*Ww + x0)*4],     w01, acc);
            corner_acc(base[((size_t)(y0+1)*Ww + x0 + 1)*4], w11, acc);
        }
    }
    uint4 o;
    o.x = pk2(acc[0].x, acc[0].y);
    o.y = pk2(acc[1].x, acc[1].y);
    o.z = pk2(acc[2].x, acc[2].y);
    o.w = pk2(acc[3].x, acc[3].y);
    *((uint4*)(g_featp + (size_t)pix*32) + q) = o;
}

// ---------------- conv1: 9-tap bf16 MMA, M=256, + sigmoid*d -> attdp ------
// block: 256 thr (8 warps), each warp 32 flat pixels (2 m-subtiles of 16)
__global__ void __launch_bounds__(256, 3) k_conv1mma(const float* __restrict__ dten,
                                                     const float* __restrict__ batt) {
    extern __shared__ unsigned char smem[];
    unsigned char* s_strip = smem;                       // STRIP1*SPITCH = 46560
    uint32_t* s_bf = (uint32_t*)(smem + STRIP1*SPITCH);  // 4608 u32 = 18432
    int rb = blockIdx.y, tile = blockIdx.x;
    int p0 = tile * MTILE, base = p0 - 163;
    int t = threadIdx.x;
    const unsigned char* fp = (const unsigned char*)(g_featp + (size_t)rb * PADPIX * 32);

    // async strip fill (zero-fill OOB), overlapped with weight-frag loads
    uint32_t sbase = smem_u32(s_strip);
    for (int e = t; e < STRIP1*4; e += 256) {
        int r = e >> 2, j = e & 3;
        int gr = base + r;
        bool v = (gr >= 0 && gr < PADPIX);
        cpa16(sbase + r*SPITCH + j*16, fp + (size_t)(v ? gr : 0)*64 + j*16, v);
    }
    asm volatile("cp.async.commit_group;" ::: "memory");
    for (int e = t; e < 4608; e += 256) s_bf[e] = g_bfrag1[e];
    asm volatile("cp.async.wait_group 0;" ::: "memory");
    __syncthreads();

    int warp = t >> 5, lane = t & 31;
    float acc[2][4][4] = {};
    uint32_t arow = sbase + (warp*32 + (lane & 15))*SPITCH + (lane >> 4)*16;

    #pragma unroll
    for (int tap = 0; tap < 9; tap++) {
        int tl = (tap/3)*PADW + (tap%3);
        #pragma unroll
        for (int kc = 0; kc < 2; kc++) {
            int kchunk = tap*2 + kc;
            uint32_t b0[4], b1[4];
            #pragma unroll
            for (int nt = 0; nt < 4; nt++) {
                b0[nt] = s_bf[kchunk*256 + nt*64 + lane*2];
                b1[nt] = s_bf[kchunk*256 + nt*64 + lane*2 + 1];
            }
            #pragma unroll
            for (int ms = 0; ms < 2; ms++) {
                uint32_t a0,a1,a2,a3;
                uint32_t addr = arow + (ms*16 + tl)*SPITCH + kc*32;
                asm volatile("ldmatrix.sync.aligned.m8n8.x4.shared.b16 {%0,%1,%2,%3}, [%4];"
                    : "=r"(a0),"=r"(a1),"=r"(a2),"=r"(a3) : "r"(addr));
                #pragma unroll
                for (int nt = 0; nt < 4; nt++) {
                    asm volatile("mma.sync.aligned.m16n8k16.row.col.f32.bf16.bf16.f32 "
                        "{%0,%1,%2,%3}, {%4,%5,%6,%7}, {%8,%9}, {%0,%1,%2,%3};"
                        : "+f"(acc[ms][nt][0]),"+f"(acc[ms][nt][1]),
                          "+f"(acc[ms][nt][2]),"+f"(acc[ms][nt][3])
                        : "r"(a0),"r"(a1),"r"(a2),"r"(a3),"r"(b0[nt]),"r"(b1[nt]));
                }
            }
        }
    }
    // epilogue: bias -> sigmoid -> * d -> attdp; borders get zeros
    int b = rb & 3;
    int colb = (lane & 3) * 2;
    #pragma unroll
    for (int ms = 0; ms < 2; ms++) {
        #pragma unroll
        for (int rr = 0; rr < 2; rr++) {
            int m = warp*32 + ms*16 + (lane >> 2) + rr*8;
            int p = p0 + m;
            if (p >= PADPIX) continue;
            int py = p / PADW, px = p - py*PADW;
            __nv_bfloat16* op = g_attdp + ((size_t)rb*PADPIX + p)*32;
            if (py >= 1 && py <= hh && px >= 1 && px <= ww) {
                int y = py - 1, x = px - 1;
                #pragma unroll
                for (int nt = 0; nt < 4; nt++) {
                    int co0 = nt*8 + colb;
                    float v0 = acc[ms][nt][rr*2]     + batt[co0];
                    float v1 = acc[ms][nt][rr*2 + 1] + batt[co0 + 1];
                    float at0 = 1.0f / (1.0f + __expf(-v0));
                    float at1 = 1.0f / (1.0f + __expf(-v1));
                    float d0 = dten[(((size_t)b*DC + co0    )*hh + y)*ww + x];
                    float d1 = dten[(((size_t)b*DC + co0 + 1)*hh + y)*ww + x];
                    *reinterpret_cast<uint32_t*>(op + co0) = pk2(at0*d0, at1*d1);
                }
            } else {
                #pragma unroll
                for (int nt = 0; nt < 4; nt++)
                    *reinterpret_cast<uint32_t*>(op + nt*8 + colb) = 0u;
            }
        }
    }
}

// ---------------- conv2: 9-tap bf16 MMA, M=256, N=8(4 real) + fused loss ---
__global__ void __launch_bounds__(256, 4) k_conv2loss(const float* __restrict__ bpost) {
    extern __shared__ unsigned char smem[];
    unsigned char* s_strip = smem;                       // STRIP1*SPITCH
    uint32_t* s_bf = (uint32_t*)(smem + STRIP1*SPITCH);  // 1152 u32
    int rb = blockIdx.y, tile = blockIdx.x;
    int p0 = tile * MTILE, base = p0 - 163;
    int t = threadIdx.x;
    const unsigned char* ap = (const unsigned char*)(g_attdp + (size_t)rb * PADPIX * 32);

    uint32_t sbase = smem_u32(s_strip);
    for (int e = t; e < STRIP1*4; e += 256) {
        int r = e >> 2, j = e & 3;
        int gr = base + r;
        bool v = (gr >= 0 && gr < PADPIX);
        cpa16(sbase + r*SPITCH + j*16, ap + (size_t)(v ? gr : 0)*64 + j*16, v);
    }
    asm volatile("cp.async.commit_group;" ::: "memory");
    for (int e = t; e < 1152; e += 256) s_bf[e] = g_bfrag2[e];
    asm volatile("cp.async.wait_group 0;" ::: "memory");
    __syncthreads();

    int warp = t >> 5, lane = t & 31;
    float acc[2][4] = {};
    uint32_t arow = sbase + (warp*32 + (lane & 15))*SPITCH + (lane >> 4)*16;

    #pragma unroll
    for (int tap = 0; tap < 9; tap++) {
        int tl = (tap/3)*PADW + (tap%3);
        #pragma unroll
        for (int kc = 0; kc < 2; kc++) {
            int kchunk = tap*2 + kc;
            uint32_t b0 = s_bf[kchunk*64 + lane*2];
            uint32_t b1 = s_bf[kchunk*64 + lane*2 + 1];
            #pragma unroll
            for (int ms = 0; ms < 2; ms++) {
                uint32_t a0,a1,a2,a3;
                uint32_t addr = arow + (ms*16 + tl)*SPITCH + kc*32;
                asm volatile("ldmatrix.sync.aligned.m8n8.x4.shared.b16 {%0,%1,%2,%3}, [%4];"
                    : "=r"(a0),"=r"(a1),"=r"(a2),"=r"(a3) : "r"(addr));
                asm volatile("mma.sync.aligned.m16n8k16.row.col.f32.bf16.bf16.f32 "
                    "{%0,%1,%2,%3}, {%4,%5,%6,%7}, {%8,%9}, {%0,%1,%2,%3};"
                    : "+f"(acc[ms][0]),"+f"(acc[ms][1]),"+f"(acc[ms][2]),"+f"(acc[ms][3])
                    : "r"(a0),"r"(a1),"r"(a2),"r"(a3),"r"(b0),"r"(b1));
            }
        }
    }

    // fused loss epilogue: ds = acc + bias; smooth-L1 against log-grads of rg
    const int dyk[4] = {0, 1, 1, 1};
    const int dxk[4] = {1, 1, 0, -1};
    float num = 0.0f, den = 0.0f;
    int colb = (lane & 3) * 2;   // co pair; only colb<4 contributes
    const float* rgp = g_rg + (size_t)rb * NPIX;
    if (colb < 4) {
        float bb0 = bpost[colb], bb1 = bpost[colb + 1];
        #pragma unroll
        for (int ms = 0; ms < 2; ms++) {
            #pragma unroll
            for (int rr = 0; rr < 2; rr++) {
                int m = warp*32 + ms*16 + (lane >> 2) + rr*8;
                int p = p0 + m;
                if (p >= PADPIX) continue;
                int py = p / PADW, px = p - py*PADW;
                if (py < 1 || py > hh || px < 1 || px > ww) continue;
                int y = py - 1, x = px - 1;
                float c = rgp[y*ww + x];
                if (c <= 0.1f) continue;
                float logc = __logf(c + EPSF);
                float ds[2] = { acc[ms][rr*2] + bb0, acc[ms][rr*2 + 1] + bb1 };
                #pragma unroll
                for (int cc = 0; cc < 2; cc++) {
                    int k = colb + cc;
                    int yn = y + dyk[k], xn = x + dxk[k];
                    if (yn < hh && xn >= 0 && xn < ww) {
                        float nb = rgp[yn*ww + xn];
                        if (nb > 0.1f) {
                            float grad = logc - __logf(nb + EPSF);
                            float a = fabsf(ds[cc] - grad);
                            float s = (a < BETAF) ? (0.5f/BETAF)*a*a : a - 0.5f*BETAF;
                            num += s; den += 1.0f;
                        }
                    }
                }
            }
        }
    }
    #pragma unroll
    for (int o = 16; o > 0; o >>= 1) {
        num += __shfl_down_sync(0xffffffffu, num, o);
        den += __shfl_down_sync(0xffffffffu, den, o);
    }
    if (lane == 0 && (num != 0.0f || den != 0.0f)) {
        int r = rb >> 2;
        atomicAdd(&g_num[r], num);
        atomicAdd(&g_den[r], den);
    }
}

// ---------------- final: mean of per-r ratios ----------------
__global__ void k_final(float* __restrict__ out) {
    int t = threadIdx.x;
    float v = (t < Rn) ? (g_num[t] / g_den[t]) : 0.0f;
    #pragma unroll
    for (int o = 16; o > 0; o >>= 1) v += __shfl_down_sync(0xffffffffu, v, o);
    if (t == 0) out[0] = v / (float)Rn;
}

// ---------------- launch ----------------
extern "C" void kernel_launch(void* const* d_in, const int* in_sizes, int n_in,
                              void* d_out, int out_size) {
    const float* x     = (const float*)d_in[0];
    const float* dten  = (const float*)d_in[1];
    const float* gts   = (const float*)d_in[2];
    const float* rnd   = (const float*)d_in[3];
    const float* Watt  = (const float*)d_in[4];
    const float* batt  = (const float*)d_in[5];
    const float* Wpost = (const float*)d_in[6];
    const float* bpost = (const float*)d_in[7];
    float* out = (float*)d_out;

    static int attr_done = 0;
    if (!attr_done) {
        cudaFuncSetAttribute(k_conv1mma, cudaFuncAttributeMaxDynamicSharedMemorySize,
                             STRIP1*SPITCH + 4608*4);
        cudaFuncSetAttribute(k_conv2loss, cudaFuncAttributeMaxDynamicSharedMemorySize,
                             STRIP1*SPITCH + 1152*4);
        attr_done = 1;
    }

    k_tp_prep<<<TPBLKS + 12, 256>>>(x, Watt, Wpost);
    k_pool<<<TOTPX/256, 256>>>(gts, rnd);
    {
        long long tp = (long long)TOTPAD * 4;
        k_samplep<<<(unsigned)((tp + 255)/256), 256>>>();
    }
    k_conv1mma<<<dim3(TILES1, RB), 256, STRIP1*SPITCH + 4608*4>>>(dten, batt);
    k_conv2loss<<<dim3(TILES1, RB), 256, STRIP1*SPITCH + 1152*4>>>(bpost);
    k_final<<<1, 32>>>(out);
}

// round 8
// speedup vs baseline: 3.2090x; 1.1469x over previous
#include <cuda_runtime.h>
#include <cuda_bf16.h>
#include <cstdint>

// ---------------- problem constants ----------------
#define Rn     20
#define NB     4
#define Hh     480
#define Ww     640
#define hh     120
#define ww     160
#define FC     32
#define DC     32
#define NPIX   (hh*ww)           // 19200
#define NPIXH  (Hh*Ww)           // 307200
#define TOTPX  (Rn*NB*NPIX)      // 1,536,000
#define RB     (Rn*NB)           // 80
#define PADH   (hh+2)            // 122
#define PADW   (ww+2)            // 162
#define PADPIX (PADH*PADW)       // 19764
#define TOTPAD (RB*PADPIX)       // 1,581,120
#define MTILE  256
#define TILES1 78                // ceil(PADPIX/256)
#define STRIP1 582               // 256 + 2*163
#define SPITCH 80                // smem row pitch (bytes)
#define BIAS_I 1282
#define EPSF   1e-6f
#define BETAF  0.01f
#define TPBLKS 38400             // transpose blocks (20*480*4)

// ---------------- device scratch ----------------
__device__ __nv_bfloat16 g_xTb[(size_t)NB*Hh*Ww*FC];      // [b][y][x][c] bf16
__device__ uint32_t     g_bfrag1[18*4*32*2];              // conv1 B fragments
__device__ uint32_t     g_bfrag2[18*32*2];                // conv2 B fragments
__device__ float        g_rg[TOTPX];
__device__ float        g_cx[TOTPX];
__device__ float        g_cy[TOTPX];
__device__ __nv_bfloat16 g_featp[(size_t)RB*PADPIX*32];   // padded, channel-last
__device__ __nv_bfloat16 g_attdp[(size_t)RB*PADPIX*32];   // padded, channel-last
__device__ float        g_num[Rn];
__device__ float        g_den[Rn];

// ---------------- helpers ----------------
__device__ __forceinline__ uint32_t smem_u32(const void* p) {
    uint32_t a;
    asm("{ .reg .u64 t; cvta.to.shared.u64 t, %1; cvt.u32.u64 %0, t; }"
        : "=r"(a) : "l"(p));
    return a;
}
__device__ __forceinline__ uint32_t pk2(float lo, float hi) {
    uint16_t l = __bfloat16_as_ushort(__float2bfloat16_rn(lo));
    uint16_t h = __bfloat16_as_ushort(__float2bfloat16_rn(hi));
    return (uint32_t)l | ((uint32_t)h << 16);
}
// accumulate 8 bf16 (uint4) * w into 4 float2
__device__ __forceinline__ void corner_acc(const uint4& v, float w, float2 acc[4]) {
    uint32_t u[4] = {v.x, v.y, v.z, v.w};
    #pragma unroll
    for (int i = 0; i < 4; i++) {
        float lo = __uint_as_float(u[i] << 16);
        float hi = __uint_as_float(u[i] & 0xffff0000u);
        acc[i].x = fmaf(w, lo, acc[i].x);
        acc[i].y = fmaf(w, hi, acc[i].y);
    }
}
// 16B cp.async with zero-fill when invalid
__device__ __forceinline__ void cpa16(uint32_t dst, const void* src, bool valid) {
    int sz = valid ? 16 : 0;
    asm volatile("cp.async.cg.shared.global [%0], [%1], 16, %2;"
                 :: "r"(dst), "l"(src), "r"(sz));
}

// ---------------- fused: x transpose + weight fragments + zero accums ------
__global__ void __launch_bounds__(256) k_tp_prep(const float* __restrict__ x,
                                                 const float* __restrict__ wa,
                                                 const float* __restrict__ wp) {
    if (blockIdx.x < TPBLKS) {
        __shared__ float tile[32][33];
        int bid = blockIdx.x;
        int xb = bid % 20; int y = (bid / 20) % Hh; int b = bid / (20 * Hh);
        int x0 = xb * 32;
        int tx = threadIdx.x & 31, ty = threadIdx.x >> 5;
        for (int c = ty; c < 32; c += 8)
            tile[c][tx] = x[(((size_t)b*32 + c)*Hh + y)*Ww + x0 + tx];
        __syncthreads();
        for (int xx = ty; xx < 32; xx += 8)
            g_xTb[(((size_t)b*Hh + y)*Ww + x0 + xx)*32 + tx] =
                __float2bfloat16_rn(tile[tx][xx]);
        return;
    }
    int e = (blockIdx.x - TPBLKS) * 256 + threadIdx.x;
    if (e < 2304) {             // conv1: 18 kchunks x 4 ntiles x 32 lanes
        int lane = e & 31, nt = (e >> 5) & 3, kchunk = e >> 7;
        int tap = kchunk >> 1, kc = kchunk & 1;
        int ky = tap / 3, kx = tap % 3;
        int n  = nt * 8 + (lane >> 2);
        int ci = kc * 16 + (lane & 3) * 2;
        float w0 = wa[((n*32 + ci    )*3 + ky)*3 + kx];
        float w1 = wa[((n*32 + ci + 1)*3 + ky)*3 + kx];
        float w2 = wa[((n*32 + ci + 8)*3 + ky)*3 + kx];
        float w3 = wa[((n*32 + ci + 9)*3 + ky)*3 + kx];
        g_bfrag1[e*2 + 0] = pk2(w0, w1);
        g_bfrag1[e*2 + 1] = pk2(w2, w3);
    } else if (e < 2880) {      // conv2: 18 kchunks x 32 lanes
        int e2 = e - 2304;
        int lane = e2 & 31, kchunk = e2 >> 5;
        int tap = kchunk >> 1, kc = kchunk & 1;
        int ky = tap / 3, kx = tap % 3;
        int n  = lane >> 2;
        int ci = kc * 16 + (lane & 3) * 2;
        float w0 = 0.f, w1 = 0.f, w2 = 0.f, w3 = 0.f;
        if (n < 4) {
            w0 = wp[((n*32 + ci    )*3 + ky)*3 + kx];
            w1 = wp[((n*32 + ci + 1)*3 + ky)*3 + kx];
            w2 = wp[((n*32 + ci + 8)*3 + ky)*3 + kx];
            w3 = wp[((n*32 + ci + 9)*3 + ky)*3 + kx];
        }
        g_bfrag2[e2*2 + 0] = pk2(w0, w1);
        g_bfrag2[e2*2 + 1] = pk2(w2, w3);
    } else if (e < 2880 + Rn) {
        g_num[e - 2880] = 0.0f;
        g_den[e - 2880] = 0.0f;
    }
}

// ---------------- random pooling + coordinate maps ----------------
__global__ void k_pool(const float* __restrict__ gts, const float* __restrict__ rnd) {
    int tid = blockIdx.x * 256 + threadIdx.x;
    if (tid >= TOTPX) return;
    int ox = tid % ww; int t2 = tid / ww;
    int oy = t2 % hh;  t2 /= hh;
    int b  = t2 % NB;  int r = t2 / NB;
    const float* rp = rnd + (size_t)(r*NB + b) * NPIXH;
    const float* gp = gts + (size_t)b * NPIXH;
    int gy0 = oy * 4, gx0 = ox * 4;
    float best = -1.0f; int bi = 0, bj = 0;
    #pragma unroll
    for (int i = 0; i < 4; i++) {
        const float4 rv = *(const float4*)(rp + (size_t)(gy0 + i)*Ww + gx0);
        const float4 gv = *(const float4*)(gp + (size_t)(gy0 + i)*Ww + gx0);
        float rr[4] = {rv.x, rv.y, rv.z, rv.w};
        float gg[4] = {gv.x, gv.y, gv.z, gv.w};
        #pragma unroll
        for (int j = 0; j < 4; j++) {
            float m = (gg[j] > 0.1f) ? rr[j] : 0.0f;
            if (m > best) { best = m; bi = i; bj = j; }
        }
    }
    int row = gy0 + bi, col = gx0 + bj;
    float g = gp[(size_t)row*Ww + col];
    g_rg[tid] = (g < 0.1f) ? 0.0f : g;
    int idx = row * Ww + col + BIAS_I;
    int qy = idx / Ww; int qx = idx - qy * Ww;
    g_cx[tid] = ((float)qx / (float)Ww) * (float)(Ww - 1);
    g_cy[tid] = ((float)qy / (float)Hh) * (float)(Hh - 1);
}

// ---------------- bilinear gather: 4 lanes/pixel, uint4 corner loads -------
__global__ void __launch_bounds__(256) k_samplep() {
    int gid = blockIdx.x * 256 + threadIdx.x;
    int pix = gid >> 2;          // padded pixel index
    int q   = gid & 3;           // channel quad (8 channels = 16B)
    if (pix >= TOTPAD) return;
    int p  = pix % PADPIX;
    int rb = pix / PADPIX;
    int py = p / PADW, px = p - py * PADW;
    float2 acc[4] = {{0.f,0.f},{0.f,0.f},{0.f,0.f},{0.f,0.f}};
    if (py >= 1 && py <= hh && px >= 1 && px <= ww) {
        int tid = rb * NPIX + (py - 1) * ww + (px - 1);
        float cx = g_cx[tid], cy = g_cy[tid];
        float fx = floorf(cx), fy = floorf(cy);
        int x0 = (int)fx, y0 = (int)fy;
        float wx = cx - fx, wy = cy - fy;
        int b = rb & 3;
        const uint4* base = (const uint4*)(g_xTb + (size_t)b * Hh * Ww * 32) + q;
        float w00 = (1.f - wx) * (1.f - wy), w10 = wx * (1.f - wy);
        float w01 = (1.f - wx) * wy,         w11 = wx * wy;
        if (y0 <= Hh - 1) {
            corner_acc(base[((size_t)y0*Ww + x0)*4],     w00, acc);
            corner_acc(base[((size_t)y0*Ww + x0 + 1)*4], w10, acc);
        }
        if (y0 + 1 <= Hh - 1) {
            corner_acc(base[((size_t)(y0+1)*Ww + x0)*4],     w01, acc);
            corner_acc(base[((size_t)(y0+1)*Ww + x0 + 1)*4], w11, acc);
        }
    }
    uint4 o;
    o.x = pk2(acc[0].x, acc[0].y);
    o.y = pk2(acc[1].x, acc[1].y);
    o.z = pk2(acc[2].x, acc[2].y);
    o.w = pk2(acc[3].x, acc[3].y);
    *((uint4*)(g_featp + (size_t)pix*32) + q) = o;
}

// ---------------- conv1: 9-tap bf16 MMA, M=256, + sigmoid*d -> attdp ------
// block: 256 thr (8 warps), warp = 32 flat px; B frags via LDG (L1-resident)
__global__ void __launch_bounds__(256, 4) k_conv1mma(const float* __restrict__ dten,
                                                     const float* __restrict__ batt) {
    extern __shared__ unsigned char smem[];
    unsigned char* s_strip = smem;                       // STRIP1*SPITCH = 46560
    int rb = blockIdx.y, tile = blockIdx.x;
    int p0 = tile * MTILE, base = p0 - 163;
    int t = threadIdx.x;
    const unsigned char* fp = (const unsigned char*)(g_featp + (size_t)rb * PADPIX * 32);

    // async strip fill (zero-fill OOB)
    uint32_t sbase = smem_u32(s_strip);
    for (int e = t; e < STRIP1*4; e += 256) {
        int r = e >> 2, j = e & 3;
        int gr = base + r;
        bool v = (gr >= 0 && gr < PADPIX);
        cpa16(sbase + r*SPITCH + j*16, fp + (size_t)(v ? gr : 0)*64 + j*16, v);
    }
    asm volatile("cp.async.commit_group;" ::: "memory");
    asm volatile("cp.async.wait_group 0;" ::: "memory");
    __syncthreads();

    int warp = t >> 5, lane = t & 31;
    float acc[2][4][4] = {};
    uint32_t arow = sbase + (warp*32 + (lane & 15))*SPITCH + (lane >> 4)*16;
    const uint2* bfr = (const uint2*)g_bfrag1 + lane;    // per-lane base

    #pragma unroll
    for (int tap = 0; tap < 9; tap++) {
        int tl = (tap/3)*PADW + (tap%3);
        #pragma unroll
        for (int kc = 0; kc < 2; kc++) {
            int kchunk = tap*2 + kc;
            uint2 bb[4];
            #pragma unroll
            for (int nt = 0; nt < 4; nt++)
                bb[nt] = __ldg(bfr + kchunk*128 + nt*32);
            #pragma unroll
            for (int ms = 0; ms < 2; ms++) {
                uint32_t a0,a1,a2,a3;
                uint32_t addr = arow + (ms*16 + tl)*SPITCH + kc*32;
                asm volatile("ldmatrix.sync.aligned.m8n8.x4.shared.b16 {%0,%1,%2,%3}, [%4];"
                    : "=r"(a0),"=r"(a1),"=r"(a2),"=r"(a3) : "r"(addr));
                #pragma unroll
                for (int nt = 0; nt < 4; nt++) {
                    asm volatile("mma.sync.aligned.m16n8k16.row.col.f32.bf16.bf16.f32 "
                        "{%0,%1,%2,%3}, {%4,%5,%6,%7}, {%8,%9}, {%0,%1,%2,%3};"
                        : "+f"(acc[ms][nt][0]),"+f"(acc[ms][nt][1]),
                          "+f"(acc[ms][nt][2]),"+f"(acc[ms][nt][3])
                        : "r"(a0),"r"(a1),"r"(a2),"r"(a3),"r"(bb[nt].x),"r"(bb[nt].y));
                }
            }
        }
    }
    // epilogue: bias -> sigmoid -> * d -> attdp; borders get zeros
    int b = rb & 3;
    int colb = (lane & 3) * 2;
    #pragma unroll
    for (int ms = 0; ms < 2; ms++) {
        #pragma unroll
        for (int rr = 0; rr < 2; rr++) {
            int m = warp*32 + ms*16 + (lane >> 2) + rr*8;
            int p = p0 + m;
            if (p >= PADPIX) continue;
            int py = p / PADW, px = p - py*PADW;
            __nv_bfloat16* op = g_attdp + ((size_t)rb*PADPIX + p)*32;
            if (py >= 1 && py <= hh && px >= 1 && px <= ww) {
                int y = py - 1, x = px - 1;
                #pragma unroll
                for (int nt = 0; nt < 4; nt++) {
                    int co0 = nt*8 + colb;
                    float v0 = acc[ms][nt][rr*2]     + batt[co0];
                    float v1 = acc[ms][nt][rr*2 + 1] + batt[co0 + 1];
                    float at0 = 1.0f / (1.0f + __expf(-v0));
                    float at1 = 1.0f / (1.0f + __expf(-v1));
                    float d0 = dten[(((size_t)b*DC + co0    )*hh + y)*ww + x];
                    float d1 = dten[(((size_t)b*DC + co0 + 1)*hh + y)*ww + x];
                    *reinterpret_cast<uint32_t*>(op + co0) = pk2(at0*d0, at1*d1);
                }
            } else {
                #pragma unroll
                for (int nt = 0; nt < 4; nt++)
                    *reinterpret_cast<uint32_t*>(op + nt*8 + colb) = 0u;
            }
        }
    }
}

// ---------------- conv2: 9-tap bf16 MMA, M=256, N=8(4 real) + fused loss ---
__global__ void __launch_bounds__(256, 4) k_conv2loss(const float* __restrict__ bpost) {
    extern __shared__ unsigned char smem[];
    unsigned char* s_strip = smem;                       // STRIP1*SPITCH
    uint32_t* s_bf = (uint32_t*)(smem + STRIP1*SPITCH);  // 1152 u32
    int rb = blockIdx.y, tile = blockIdx.x;
    int p0 = tile * MTILE, base = p0 - 163;
    int t = threadIdx.x;
    const unsigned char* ap = (const unsigned char*)(g_attdp + (size_t)rb * PADPIX * 32);

    uint32_t sbase = smem_u32(s_strip);
    for (int e = t; e < STRIP1*4; e += 256) {
        int r = e >> 2, j = e & 3;
        int gr = base + r;
        bool v = (gr >= 0 && gr < PADPIX);
        cpa16(sbase + r*SPITCH + j*16, ap + (size_t)(v ? gr : 0)*64 + j*16, v);
    }
    asm volatile("cp.async.commit_group;" ::: "memory");
    for (int e = t; e < 1152; e += 256) s_bf[e] = g_bfrag2[e];
    asm volatile("cp.async.wait_group 0;" ::: "memory");
    __syncthreads();

    int warp = t >> 5, lane = t & 31;
    float acc[2][4] = {};
    uint32_t arow = sbase + (warp*32 + (lane & 15))*SPITCH + (lane >> 4)*16;

    #pragma unroll
    for (int tap = 0; tap < 9; tap++) {
        int tl = (tap/3)*PADW + (tap%3);
        #pragma unroll
        for (int kc = 0; kc < 2; kc++) {
            int kchunk = tap*2 + kc;
            uint32_t b0 = s_bf[kchunk*64 + lane*2];
            uint32_t b1 = s_bf[kchunk*64 + lane*2 + 1];
            #pragma unroll
            for (int ms = 0; ms < 2; ms++) {
                uint32_t a0,a1,a2,a3;
                uint32_t addr = arow + (ms*16 + tl)*SPITCH + kc*32;
                asm volatile("ldmatrix.sync.aligned.m8n8.x4.shared.b16 {%0,%1,%2,%3}, [%4];"
                    : "=r"(a0),"=r"(a1),"=r"(a2),"=r"(a3) : "r"(addr));
                asm volatile("mma.sync.aligned.m16n8k16.row.col.f32.bf16.bf16.f32 "
                    "{%0,%1,%2,%3}, {%4,%5,%6,%7}, {%8,%9}, {%0,%1,%2,%3};"
                    : "+f"(acc[ms][0]),"+f"(acc[ms][1]),"+f"(acc[ms][2]),"+f"(acc[ms][3])
                    : "r"(a0),"r"(a1),"r"(a2),"r"(a3),"r"(b0),"r"(b1));
            }
        }
    }

    // fused loss epilogue: ds = acc + bias; smooth-L1 against log-grads of rg
    const int dyk[4] = {0, 1, 1, 1};
    const int dxk[4] = {1, 1, 0, -1};
    float num = 0.0f, den = 0.0f;
    int colb = (lane & 3) * 2;   // co pair; only colb<4 contributes
    const float* rgp = g_rg + (size_t)rb * NPIX;
    if (colb < 4) {
        float bb0 = bpost[colb], bb1 = bpost[colb + 1];
        #pragma unroll
        for (int ms = 0; ms < 2; ms++) {
            #pragma unroll
            for (int rr = 0; rr < 2; rr++) {
                int m = warp*32 + ms*16 + (lane >> 2) + rr*8;
                int p = p0 + m;
                if (p >= PADPIX) continue;
                int py = p / PADW, px = p - py*PADW;
                if (py < 1 || py > hh || px < 1 || px > ww) continue;
                int y = py - 1, x = px - 1;
                float c = rgp[y*ww + x];
                if (c <= 0.1f) continue;
                float logc = __logf(c + EPSF);
                float ds[2] = { acc[ms][rr*2] + bb0, acc[ms][rr*2 + 1] + bb1 };
                #pragma unroll
                for (int cc = 0; cc < 2; cc++) {
                    int k = colb + cc;
                    int yn = y + dyk[k], xn = x + dxk[k];
                    if (yn < hh && xn >= 0 && xn < ww) {
                        float nb = rgp[yn*ww + xn];
                        if (nb > 0.1f) {
                            float grad = logc - __logf(nb + EPSF);
                            float a = fabsf(ds[cc] - grad);
                            float s = (a < BETAF) ? (0.5f/BETAF)*a*a : a - 0.5f*BETAF;
                            num += s; den += 1.0f;
                        }
                    }
                }
            }
        }
    }
    #pragma unroll
    for (int o = 16; o > 0; o >>= 1) {
        num += __shfl_down_sync(0xffffffffu, num, o);
        den += __shfl_down_sync(0xffffffffu, den, o);
    }
    if (lane == 0 && (num != 0.0f || den != 0.0f)) {
        int r = rb >> 2;
        atomicAdd(&g_num[r], num);
        atomicAdd(&g_den[r], den);
    }
}

// ---------------- final: mean of per-r ratios ----------------
__global__ void k_final(float* __restrict__ out) {
    int t = threadIdx.x;
    float v = (t < Rn) ? (g_num[t] / g_den[t]) : 0.0f;
    #pragma unroll
    for (int o = 16; o > 0; o >>= 1) v += __shfl_down_sync(0xffffffffu, v, o);
    if (t == 0) out[0] = v / (float)Rn;
}

// ---------------- launch ----------------
extern "C" void kernel_launch(void* const* d_in, const int* in_sizes, int n_in,
                              void* d_out, int out_size) {
    const float* x     = (const float*)d_in[0];
    const float* dten  = (const float*)d_in[1];
    const float* gts   = (const float*)d_in[2];
    const float* rnd   = (const float*)d_in[3];
    const float* Watt  = (const float*)d_in[4];
    const float* batt  = (const float*)d_in[5];
    const float* Wpost = (const float*)d_in[6];
    const float* bpost = (const float*)d_in[7];
    float* out = (float*)d_out;

    static int attr_done = 0;
    if (!attr_done) {
        cudaFuncSetAttribute(k_conv1mma, cudaFuncAttributeMaxDynamicSharedMemorySize,
                             STRIP1*SPITCH);
        cudaFuncSetAttribute(k_conv2loss, cudaFuncAttributeMaxDynamicSharedMemorySize,
                             STRIP1*SPITCH + 1152*4);
        attr_done = 1;
    }

    k_tp_prep<<<TPBLKS + 12, 256>>>(x, Watt, Wpost);
    k_pool<<<TOTPX/256, 256>>>(gts, rnd);
    {
        long long tp = (long long)TOTPAD * 4;
        k_samplep<<<(unsigned)((tp + 255)/256), 256>>>();
    }
    k_conv1mma<<<dim3(TILES1, RB), 256, STRIP1*SPITCH>>>(dten, batt);
    k_conv2loss<<<dim3(TILES1, RB), 256, STRIP1*SPITCH + 1152*4>>>(bpost);
    k_final<<<1, 32>>>(out);
}